// round 1
// baseline (speedup 1.0000x reference)
#include <cuda_runtime.h>
#include <math.h>
#include <stdint.h>

#define HH 256
#define WW 256
#define HW 65536
#define NB 16
#define CC 64
#define LL 256
#define NP 256   // watermark points (all in channel 0)

// ---------------- scratch (no allocations allowed) ----------------
__device__ float g_bufA[NB * CC * HW];   // 268 MB
__device__ float g_bufB[NB * CC * HW];   // 268 MB
__device__ float g_H[NB * 21 * 256 * 2]; // column DFT at 21 distinct x-freqs
__device__ float g_d[NB * NP * 2];       // delta at watermark points
__device__ float g_R[NB * 16 * 256 * 2]; // per-row inverse partial
__device__ float g_T[NB * CC * 9];       // msg-channel conv taps
__device__ float g_scale[5 * CC];
__device__ float g_bias[5 * CC];
__device__ int   g_wy[NP];
__device__ int   g_wx[NP];

#define TWO_PI 6.283185307179586f

// ---------------- prep: fold BN, watermark indices ----------------
__global__ void prep_kernel(const float* b0, const float* g0, const float* be0,
                            const float* m0, const float* v0,
                            const float* bk, const float* gk, const float* bek,
                            const float* mk, const float* vk,
                            const float* ba, const float* ga, const float* bea,
                            const float* ma, const float* va) {
  int c = threadIdx.x;
  const float EPS = 1e-5f;
  if (c < CC) {
    float s = g0[c] * rsqrtf(v0[c] + EPS);
    g_scale[c] = s;
    g_bias[c] = be0[c] + (b0[c] - m0[c]) * s;
    for (int t = 0; t < 3; t++) {
      float st = gk[t * CC + c] * rsqrtf(vk[t * CC + c] + EPS);
      g_scale[(1 + t) * CC + c] = st;
      g_bias[(1 + t) * CC + c] = bek[t * CC + c] + (bk[t * CC + c] - mk[t * CC + c]) * st;
    }
    float sa = ga[c] * rsqrtf(va[c] + EPS);
    g_scale[4 * CC + c] = sa;
    g_bias[4 * CC + c] = bea[c] + (ba[c] - ma[c]) * sa;
  }
  if (c == 0) {
    int cnt = 0;
    for (int ch = 0; ch < CC && cnt < NP; ch++)
      for (int i = -10; i <= 10 && cnt < NP; i++)
        for (int j = -10; j <= 10; j++) {
          if (cnt >= NP) break;
          int y = 128 + i, x = 128 + j;
          if (y >= 0 && y < HH && x >= 0 && x < WW && (i * i + j * j <= 100)) {
            g_wy[cnt] = y; g_wx[cnt] = x; cnt++;
          }
        }
  }
}

// ---------------- msg-channel conv taps: T[b,o,kh,kw] ----------------
__global__ void msgT_kernel(const float* __restrict__ message,
                            const float* __restrict__ wa) {
  int o = blockIdx.x, b = blockIdx.y;
  int c = threadIdx.x;
  __shared__ float red[8];
  float mv = message[b * LL + c];
  const float* wp = wa + ((size_t)o * 323 + c) * 9;
  for (int t = 0; t < 9; t++) {
    float v = mv * wp[t];
#pragma unroll
    for (int off = 16; off > 0; off >>= 1) v += __shfl_down_sync(0xffffffffu, v, off);
    if ((c & 31) == 0) red[c >> 5] = v;
    __syncthreads();
    if (c == 0) {
      float s = 0;
      for (int w = 0; w < 8; w++) s += red[w];
      g_T[(b * CC + o) * 9 + t] = s;
    }
    __syncthreads();
  }
}

// ---------------- main tiled 3x3 conv + BN + ReLU ----------------
// block: 256 threads, 32x32 spatial tile, 16 output channels.
// input channels: buffer channels first (bufC from g_buf[bufSrc]), then extC from ext_in.
__launch_bounds__(256, 2)
__global__ void conv3x3_kernel(const float* __restrict__ ext_in, int extC,
                               int bufSrc, int bufC, int bufDst,
                               const float* __restrict__ Wt, int CW, int ic0,
                               int layer, int use_msg) {
  __shared__ __align__(16) float w_s[67 * 144];
  __shared__ float tile[34 * 34];
  __shared__ float T_s[16 * 9];

  float* bufs[2] = {g_bufA, g_bufB};
  const float* bsrc = (bufSrc >= 0) ? bufs[bufSrc] : nullptr;
  float* out = bufs[bufDst];

  int tid = threadIdx.x;
  int tileId = blockIdx.x, ocg = blockIdx.y, b = blockIdx.z;
  int y0 = (tileId >> 3) << 5, x0 = (tileId & 7) << 5;
  int Ctot = bufC + extC;

  // stage all weights for this oc-group: layout [c][tap][oc16]
  int Wstride = CW * 9;
  for (int idx = tid; idx < Ctot * 144; idx += 256) {
    int c = idx / 144;
    int rem = idx - c * 144;
    int t = rem >> 4;
    int oc = rem & 15;
    w_s[idx] = Wt[(size_t)(ocg * 16 + oc) * Wstride + (ic0 + c) * 9 + t];
  }
  if (use_msg && tid < 144)
    T_s[tid] = g_T[(b * CC + ocg * 16 + (tid / 9)) * 9 + (tid % 9)];
  __syncthreads();

  int tx = tid & 31, ty = tid >> 5;
  float acc[4][16];
#pragma unroll
  for (int k = 0; k < 4; k++)
#pragma unroll
    for (int o = 0; o < 16; o++) acc[k][o] = 0.f;

  // message-channel contribution (constant per pixel except borders)
  if (use_msg) {
#pragma unroll
    for (int k = 0; k < 4; k++) {
      int y = y0 + ty + 8 * k;
      int x = x0 + tx;
#pragma unroll
      for (int kh = 0; kh < 3; kh++) {
        int iy = y + kh - 1;
        bool vy = (iy >= 0) && (iy < HH);
#pragma unroll
        for (int kw = 0; kw < 3; kw++) {
          int ix = x + kw - 1;
          if (vy && ix >= 0 && ix < WW) {
#pragma unroll
            for (int o = 0; o < 16; o++) acc[k][o] += T_s[o * 9 + kh * 3 + kw];
          }
        }
      }
    }
  }

  for (int c = 0; c < Ctot; c++) {
    __syncthreads();
    const float* src = (c < bufC)
        ? (bsrc + ((size_t)(b * bufC + c)) * HW)
        : (ext_in + ((size_t)(b * extC + (c - bufC))) * HW);
    for (int idx = tid; idx < 34 * 34; idx += 256) {
      int r = idx / 34, cl = idx - r * 34;
      int gy = y0 + r - 1, gx = x0 + cl - 1;
      float v = 0.f;
      if (gy >= 0 && gy < HH && gx >= 0 && gx < WW) v = src[gy * WW + gx];
      tile[idx] = v;
    }
    __syncthreads();

    const float* wc = w_s + c * 144;
#pragma unroll
    for (int kh = 0; kh < 3; kh++) {
#pragma unroll
      for (int kw = 0; kw < 3; kw++) {
        int t = kh * 3 + kw;
        float4 wv0 = *(const float4*)(wc + t * 16);
        float4 wv1 = *(const float4*)(wc + t * 16 + 4);
        float4 wv2 = *(const float4*)(wc + t * 16 + 8);
        float4 wv3 = *(const float4*)(wc + t * 16 + 12);
#pragma unroll
        for (int k = 0; k < 4; k++) {
          float v = tile[(ty + 8 * k + kh) * 34 + tx + kw];
          acc[k][0] += v * wv0.x;  acc[k][1] += v * wv0.y;
          acc[k][2] += v * wv0.z;  acc[k][3] += v * wv0.w;
          acc[k][4] += v * wv1.x;  acc[k][5] += v * wv1.y;
          acc[k][6] += v * wv1.z;  acc[k][7] += v * wv1.w;
          acc[k][8] += v * wv2.x;  acc[k][9] += v * wv2.y;
          acc[k][10] += v * wv2.z; acc[k][11] += v * wv2.w;
          acc[k][12] += v * wv3.x; acc[k][13] += v * wv3.y;
          acc[k][14] += v * wv3.z; acc[k][15] += v * wv3.w;
        }
      }
    }
  }

  const float* scp = g_scale + layer * CC + ocg * 16;
  const float* bip = g_bias + layer * CC + ocg * 16;
#pragma unroll
  for (int k = 0; k < 4; k++) {
    int y = y0 + ty + 8 * k;
    size_t base = ((size_t)(b * CC + ocg * 16)) * HW + (size_t)y * WW + x0 + tx;
#pragma unroll
    for (int o = 0; o < 16; o++) {
      float r = acc[k][o] * scp[o] + bip[o];
      out[base + (size_t)o * HW] = r > 0.f ? r : 0.f;
    }
  }
}

// ---------------- sparse-frequency DFT chain (channel 0 of g_bufB) ----------
// H[b,f,n] = sum_m x[b,0,n,m] * e^{-2pi i (118+f) m / 256}
__global__ void dft_rows_kernel() {
  int n = blockIdx.x, b = blockIdx.y;
  int m = threadIdx.x;
  __shared__ float row[256], twc[256], tws[256], red[16];
  float s, c;
  sincosf((float)m * (TWO_PI / 256.f), &s, &c);
  twc[m] = c; tws[m] = s;
  row[m] = g_bufB[((size_t)b * CC) * HW + (size_t)n * WW + m];
  __syncthreads();
  float x = row[m];
  int lane = m & 31, wid = m >> 5;
  for (int f = 0; f < 21; f++) {
    int idx = ((118 + f) * m) & 255;
    float pr = x * twc[idx];
    float pi = -x * tws[idx];
#pragma unroll
    for (int off = 16; off > 0; off >>= 1) {
      pr += __shfl_down_sync(0xffffffffu, pr, off);
      pi += __shfl_down_sync(0xffffffffu, pi, off);
    }
    if (lane == 0) { red[wid] = pr; red[8 + wid] = pi; }
    __syncthreads();
    if (m == 0) {
      float sr = 0, si = 0;
      for (int w = 0; w < 8; w++) { sr += red[w]; si += red[8 + w]; }
      g_H[((size_t)(b * 21 + f) * 256 + n) * 2] = sr;
      g_H[((size_t)(b * 21 + f) * 256 + n) * 2 + 1] = si;
    }
    __syncthreads();
  }
}

// F[b,p] = sum_n e^{-2pi i y_p n/256} H[b, f(x_p), n];  d = (msg + i msg) - F
__global__ void dft_points_kernel(const float* __restrict__ message) {
  int b = blockIdx.x;
  int p = threadIdx.x;
  __shared__ float twc[256], tws[256];
  float s, c;
  sincosf((float)p * (TWO_PI / 256.f), &s, &c);
  twc[p] = c; tws[p] = s;
  __syncthreads();
  int yp = g_wy[p], xp = g_wx[p];
  int f = xp - 118;
  const float* Hp = g_H + (size_t)(b * 21 + f) * 512;
  float Fr = 0, Fi = 0;
  for (int n = 0; n < 256; n++) {
    int idx = (yp * n) & 255;
    float cc = twc[idx], ss = tws[idx];
    float hr = Hp[n * 2], hi = Hp[n * 2 + 1];
    Fr += hr * cc + hi * ss;   // e^{-i t} * H
    Fi += hi * cc - hr * ss;
  }
  float mv = message[b * LL + p];
  g_d[(b * NP + p) * 2] = mv - Fr;
  g_d[(b * NP + p) * 2 + 1] = mv - Fi;
}

// R[b,yf,m] = sum_{p: y_p = 118+yf} d_p e^{+2pi i x_p m/256}
__global__ void dft_R_kernel() {
  int yf = blockIdx.x, b = blockIdx.y;
  int m = threadIdx.x;
  __shared__ float twc[256], tws[256], dsr[256], dsi[256];
  float s, c;
  sincosf((float)m * (TWO_PI / 256.f), &s, &c);
  twc[m] = c; tws[m] = s;
  dsr[m] = g_d[(b * NP + m) * 2];
  dsi[m] = g_d[(b * NP + m) * 2 + 1];
  __syncthreads();
  int yv = 118 + yf;
  float ar = 0, ai = 0;
  for (int p = 0; p < NP; p++) {
    if (g_wy[p] == yv) {
      int idx = (g_wx[p] * m) & 255;
      float cc = twc[idx], ss = tws[idx];
      float dr = dsr[p], di = dsi[p];
      ar += dr * cc - di * ss;
      ai += dr * ss + di * cc;
    }
  }
  g_R[((size_t)(b * 16 + yf) * 256 + m) * 2] = ar;
  g_R[((size_t)(b * 16 + yf) * 256 + m) * 2 + 1] = ai;
}

// corr[b,n,m] = (1/65536) sum_yf Re[e^{+2pi i (118+yf) n /256} R[b,yf,m]]; add into bufB ch0
__global__ void dft_corr_kernel() {
  int n = blockIdx.x, b = blockIdx.y;
  int m = threadIdx.x;
  __shared__ float twc[256], tws[256];
  float s, c;
  sincosf((float)m * (TWO_PI / 256.f), &s, &c);
  twc[m] = c; tws[m] = s;
  __syncthreads();
  float acc = 0.f;
#pragma unroll
  for (int yf = 0; yf < 16; yf++) {
    int idx = ((118 + yf) * n) & 255;
    float cc = twc[idx], ss = tws[idx];
    float Rr = g_R[((size_t)(b * 16 + yf) * 256 + m) * 2];
    float Ri = g_R[((size_t)(b * 16 + yf) * 256 + m) * 2 + 1];
    acc += cc * Rr - ss * Ri;
  }
  g_bufB[((size_t)b * CC) * HW + (size_t)n * WW + m] += acc * (1.0f / 65536.0f);
}

// ---------------- final 1x1 projection ----------------
__global__ void proj_kernel(const float* __restrict__ wf, const float* __restrict__ bf,
                            float* __restrict__ out) {
  int tid = threadIdx.x;
  __shared__ float wfs[192];
  if (tid < 192) wfs[tid] = wf[tid];
  __syncthreads();
  int P = blockIdx.x * 256 + tid;
  int b = P >> 16;
  int pix = P & 65535;
  const float* src = g_bufA + (size_t)b * CC * HW + pix;
  float a0 = bf[0], a1 = bf[1], a2 = bf[2];
#pragma unroll
  for (int c = 0; c < CC; c++) {
    float v = src[(size_t)c * HW];
    a0 += v * wfs[c];
    a1 += v * wfs[64 + c];
    a2 += v * wfs[128 + c];
  }
  size_t ob = ((size_t)b * 3) * HW + pix;
  out[ob] = a0;
  out[ob + HW] = a1;
  out[ob + 2 * HW] = a2;
}

// ---------------- launch ----------------
extern "C" void kernel_launch(void* const* d_in, const int* in_sizes, int n_in,
                              void* d_out, int out_size) {
  const float* image   = (const float*)d_in[0];
  const float* message = (const float*)d_in[1];
  const float* w0  = (const float*)d_in[2];
  const float* b0  = (const float*)d_in[3];
  const float* g0  = (const float*)d_in[4];
  const float* be0 = (const float*)d_in[5];
  const float* m0  = (const float*)d_in[6];
  const float* v0  = (const float*)d_in[7];
  const float* wk  = (const float*)d_in[8];
  const float* bk  = (const float*)d_in[9];
  const float* gk  = (const float*)d_in[10];
  const float* bek = (const float*)d_in[11];
  const float* mk  = (const float*)d_in[12];
  const float* vk  = (const float*)d_in[13];
  const float* wa  = (const float*)d_in[14];
  const float* ba  = (const float*)d_in[15];
  const float* ga  = (const float*)d_in[16];
  const float* bea = (const float*)d_in[17];
  const float* ma  = (const float*)d_in[18];
  const float* va  = (const float*)d_in[19];
  const float* wf  = (const float*)d_in[20];
  const float* bf  = (const float*)d_in[21];
  float* out = (float*)d_out;

  prep_kernel<<<1, 256>>>(b0, g0, be0, m0, v0, bk, gk, bek, mk, vk, ba, ga, bea, ma, va);

  dim3 cg(64, 4, NB);
  // conv0: image(3) -> bufA
  conv3x3_kernel<<<cg, 256>>>(image, 3, -1, 0, 0, w0, 3, 0, 0, 0);
  // k-layers: 64->64
  conv3x3_kernel<<<cg, 256>>>(nullptr, 0, 0, 64, 1, wk + 0 * 64 * 64 * 9, 64, 0, 1, 0);
  conv3x3_kernel<<<cg, 256>>>(nullptr, 0, 1, 64, 0, wk + 1 * 64 * 64 * 9, 64, 0, 2, 0);
  conv3x3_kernel<<<cg, 256>>>(nullptr, 0, 0, 64, 1, wk + 2 * 64 * 64 * 9, 64, 0, 3, 0);

  // watermark: sparse-frequency DFT correction on bufB channel 0
  dft_rows_kernel<<<dim3(256, NB), 256>>>();
  dft_points_kernel<<<NB, 256>>>(message);
  dft_R_kernel<<<dim3(16, NB), 256>>>();
  dft_corr_kernel<<<dim3(256, NB), 256>>>();

  // message-channel taps + final conv: [bufB(64) | image(3)] -> bufA (weights wa, ic offset 256)
  msgT_kernel<<<dim3(64, NB), 256>>>(message, wa);
  conv3x3_kernel<<<cg, 256>>>(image, 3, 1, 64, 0, wa, 323, 256, 4, 1);

  // 1x1 projection -> out
  proj_kernel<<<NB * HW / 256, 256>>>(wf, bf, out);
}

// round 2
// speedup vs baseline: 1.0002x; 1.0002x over previous
#include <cuda_runtime.h>
#include <math.h>
#include <stdint.h>

#define HH 256
#define WW 256
#define HW 65536
#define NB 16
#define CC 64
#define LL 256
#define NP 256   // watermark points (all in channel 0)

// ---------------- scratch (no allocations allowed) ----------------
__device__ float g_bufA[NB * CC * HW];   // 268 MB
__device__ float g_bufB[NB * CC * HW];   // 268 MB
__device__ float g_H[NB * 21 * 256 * 2]; // column DFT at 21 distinct x-freqs
__device__ float g_d[NB * NP * 2];       // delta at watermark points
__device__ float g_R[NB * 16 * 256 * 2]; // per-row inverse partial
__device__ float g_T[NB * CC * 9];       // msg-channel conv taps
__device__ float g_scale[5 * CC];
__device__ float g_bias[5 * CC];
__device__ int   g_wy[NP];
__device__ int   g_wx[NP];

#define TWO_PI 6.283185307179586f

// ---------------- prep: fold BN, watermark indices ----------------
__global__ void prep_kernel(const float* b0, const float* g0, const float* be0,
                            const float* m0, const float* v0,
                            const float* bk, const float* gk, const float* bek,
                            const float* mk, const float* vk,
                            const float* ba, const float* ga, const float* bea,
                            const float* ma, const float* va) {
  int c = threadIdx.x;
  const float EPS = 1e-5f;
  if (c < CC) {
    float s = g0[c] * rsqrtf(v0[c] + EPS);
    g_scale[c] = s;
    g_bias[c] = be0[c] + (b0[c] - m0[c]) * s;
    for (int t = 0; t < 3; t++) {
      float st = gk[t * CC + c] * rsqrtf(vk[t * CC + c] + EPS);
      g_scale[(1 + t) * CC + c] = st;
      g_bias[(1 + t) * CC + c] = bek[t * CC + c] + (bk[t * CC + c] - mk[t * CC + c]) * st;
    }
    float sa = ga[c] * rsqrtf(va[c] + EPS);
    g_scale[4 * CC + c] = sa;
    g_bias[4 * CC + c] = bea[c] + (ba[c] - ma[c]) * sa;
  }
  if (c == 0) {
    int cnt = 0;
    for (int ch = 0; ch < CC && cnt < NP; ch++)
      for (int i = -10; i <= 10 && cnt < NP; i++)
        for (int j = -10; j <= 10; j++) {
          if (cnt >= NP) break;
          int y = 128 + i, x = 128 + j;
          if (y >= 0 && y < HH && x >= 0 && x < WW && (i * i + j * j <= 100)) {
            g_wy[cnt] = y; g_wx[cnt] = x; cnt++;
          }
        }
  }
}

// ---------------- msg-channel conv taps: T[b,o,kh,kw] ----------------
__global__ void msgT_kernel(const float* __restrict__ message,
                            const float* __restrict__ wa) {
  int o = blockIdx.x, b = blockIdx.y;
  int c = threadIdx.x;
  __shared__ float red[8];
  float mv = message[b * LL + c];
  const float* wp = wa + ((size_t)o * 323 + c) * 9;
  for (int t = 0; t < 9; t++) {
    float v = mv * wp[t];
#pragma unroll
    for (int off = 16; off > 0; off >>= 1) v += __shfl_down_sync(0xffffffffu, v, off);
    if ((c & 31) == 0) red[c >> 5] = v;
    __syncthreads();
    if (c == 0) {
      float s = 0;
      for (int w = 0; w < 8; w++) s += red[w];
      g_T[(b * CC + o) * 9 + t] = s;
    }
    __syncthreads();
  }
}

// ---------------- main tiled 3x3 conv + BN + ReLU ----------------
// block: 256 threads, 32x32 spatial tile, 16 output channels.
// input channels: buffer channels first (bufC from g_buf[bufSrc]), then extC from ext_in.
__launch_bounds__(256, 2)
__global__ void conv3x3_kernel(const float* __restrict__ ext_in, int extC,
                               int bufSrc, int bufC, int bufDst,
                               const float* __restrict__ Wt, int CW, int ic0,
                               int layer, int use_msg) {
  __shared__ __align__(16) float w_s[67 * 144];
  __shared__ float tile[34 * 34];
  __shared__ float T_s[16 * 9];

  float* bufs[2] = {g_bufA, g_bufB};
  const float* bsrc = (bufSrc >= 0) ? bufs[bufSrc] : nullptr;
  float* out = bufs[bufDst];

  int tid = threadIdx.x;
  int tileId = blockIdx.x, ocg = blockIdx.y, b = blockIdx.z;
  int y0 = (tileId >> 3) << 5, x0 = (tileId & 7) << 5;
  int Ctot = bufC + extC;

  // stage all weights for this oc-group: layout [c][tap][oc16]
  int Wstride = CW * 9;
  for (int idx = tid; idx < Ctot * 144; idx += 256) {
    int c = idx / 144;
    int rem = idx - c * 144;
    int t = rem >> 4;
    int oc = rem & 15;
    w_s[idx] = Wt[(size_t)(ocg * 16 + oc) * Wstride + (ic0 + c) * 9 + t];
  }
  if (use_msg && tid < 144)
    T_s[tid] = g_T[(b * CC + ocg * 16 + (tid / 9)) * 9 + (tid % 9)];
  __syncthreads();

  int tx = tid & 31, ty = tid >> 5;
  float acc[4][16];
#pragma unroll
  for (int k = 0; k < 4; k++)
#pragma unroll
    for (int o = 0; o < 16; o++) acc[k][o] = 0.f;

  // message-channel contribution (constant per pixel except borders)
  if (use_msg) {
#pragma unroll
    for (int k = 0; k < 4; k++) {
      int y = y0 + ty + 8 * k;
      int x = x0 + tx;
#pragma unroll
      for (int kh = 0; kh < 3; kh++) {
        int iy = y + kh - 1;
        bool vy = (iy >= 0) && (iy < HH);
#pragma unroll
        for (int kw = 0; kw < 3; kw++) {
          int ix = x + kw - 1;
          if (vy && ix >= 0 && ix < WW) {
#pragma unroll
            for (int o = 0; o < 16; o++) acc[k][o] += T_s[o * 9 + kh * 3 + kw];
          }
        }
      }
    }
  }

  for (int c = 0; c < Ctot; c++) {
    __syncthreads();
    const float* src = (c < bufC)
        ? (bsrc + ((size_t)(b * bufC + c)) * HW)
        : (ext_in + ((size_t)(b * extC + (c - bufC))) * HW);
    for (int idx = tid; idx < 34 * 34; idx += 256) {
      int r = idx / 34, cl = idx - r * 34;
      int gy = y0 + r - 1, gx = x0 + cl - 1;
      float v = 0.f;
      if (gy >= 0 && gy < HH && gx >= 0 && gx < WW) v = src[gy * WW + gx];
      tile[idx] = v;
    }
    __syncthreads();

    const float* wc = w_s + c * 144;
#pragma unroll
    for (int kh = 0; kh < 3; kh++) {
#pragma unroll
      for (int kw = 0; kw < 3; kw++) {
        int t = kh * 3 + kw;
        float4 wv0 = *(const float4*)(wc + t * 16);
        float4 wv1 = *(const float4*)(wc + t * 16 + 4);
        float4 wv2 = *(const float4*)(wc + t * 16 + 8);
        float4 wv3 = *(const float4*)(wc + t * 16 + 12);
#pragma unroll
        for (int k = 0; k < 4; k++) {
          float v = tile[(ty + 8 * k + kh) * 34 + tx + kw];
          acc[k][0] += v * wv0.x;  acc[k][1] += v * wv0.y;
          acc[k][2] += v * wv0.z;  acc[k][3] += v * wv0.w;
          acc[k][4] += v * wv1.x;  acc[k][5] += v * wv1.y;
          acc[k][6] += v * wv1.z;  acc[k][7] += v * wv1.w;
          acc[k][8] += v * wv2.x;  acc[k][9] += v * wv2.y;
          acc[k][10] += v * wv2.z; acc[k][11] += v * wv2.w;
          acc[k][12] += v * wv3.x; acc[k][13] += v * wv3.y;
          acc[k][14] += v * wv3.z; acc[k][15] += v * wv3.w;
        }
      }
    }
  }

  const float* scp = g_scale + layer * CC + ocg * 16;
  const float* bip = g_bias + layer * CC + ocg * 16;
#pragma unroll
  for (int k = 0; k < 4; k++) {
    int y = y0 + ty + 8 * k;
    size_t base = ((size_t)(b * CC + ocg * 16)) * HW + (size_t)y * WW + x0 + tx;
#pragma unroll
    for (int o = 0; o < 16; o++) {
      float r = acc[k][o] * scp[o] + bip[o];
      out[base + (size_t)o * HW] = r > 0.f ? r : 0.f;
    }
  }
}

// ---------------- sparse-frequency DFT chain (channel 0 of g_bufB) ----------
// H[b,f,n] = sum_m x[b,0,n,m] * e^{-2pi i (118+f) m / 256}
__global__ void dft_rows_kernel() {
  int n = blockIdx.x, b = blockIdx.y;
  int m = threadIdx.x;
  __shared__ float row[256], twc[256], tws[256], red[16];
  float s, c;
  sincosf((float)m * (TWO_PI / 256.f), &s, &c);
  twc[m] = c; tws[m] = s;
  row[m] = g_bufB[((size_t)b * CC) * HW + (size_t)n * WW + m];
  __syncthreads();
  float x = row[m];
  int lane = m & 31, wid = m >> 5;
  for (int f = 0; f < 21; f++) {
    int idx = ((118 + f) * m) & 255;
    float pr = x * twc[idx];
    float pi = -x * tws[idx];
#pragma unroll
    for (int off = 16; off > 0; off >>= 1) {
      pr += __shfl_down_sync(0xffffffffu, pr, off);
      pi += __shfl_down_sync(0xffffffffu, pi, off);
    }
    if (lane == 0) { red[wid] = pr; red[8 + wid] = pi; }
    __syncthreads();
    if (m == 0) {
      float sr = 0, si = 0;
      for (int w = 0; w < 8; w++) { sr += red[w]; si += red[8 + w]; }
      g_H[((size_t)(b * 21 + f) * 256 + n) * 2] = sr;
      g_H[((size_t)(b * 21 + f) * 256 + n) * 2 + 1] = si;
    }
    __syncthreads();
  }
}

// F[b,p] = sum_n e^{-2pi i y_p n/256} H[b, f(x_p), n];  d = (msg + i msg) - F
__global__ void dft_points_kernel(const float* __restrict__ message) {
  int b = blockIdx.x;
  int p = threadIdx.x;
  __shared__ float twc[256], tws[256];
  float s, c;
  sincosf((float)p * (TWO_PI / 256.f), &s, &c);
  twc[p] = c; tws[p] = s;
  __syncthreads();
  int yp = g_wy[p], xp = g_wx[p];
  int f = xp - 118;
  const float* Hp = g_H + (size_t)(b * 21 + f) * 512;
  float Fr = 0, Fi = 0;
  for (int n = 0; n < 256; n++) {
    int idx = (yp * n) & 255;
    float cc = twc[idx], ss = tws[idx];
    float hr = Hp[n * 2], hi = Hp[n * 2 + 1];
    Fr += hr * cc + hi * ss;   // e^{-i t} * H
    Fi += hi * cc - hr * ss;
  }
  float mv = message[b * LL + p];
  g_d[(b * NP + p) * 2] = mv - Fr;
  g_d[(b * NP + p) * 2 + 1] = mv - Fi;
}

// R[b,yf,m] = sum_{p: y_p = 118+yf} d_p e^{+2pi i x_p m/256}
__global__ void dft_R_kernel() {
  int yf = blockIdx.x, b = blockIdx.y;
  int m = threadIdx.x;
  __shared__ float twc[256], tws[256], dsr[256], dsi[256];
  float s, c;
  sincosf((float)m * (TWO_PI / 256.f), &s, &c);
  twc[m] = c; tws[m] = s;
  dsr[m] = g_d[(b * NP + m) * 2];
  dsi[m] = g_d[(b * NP + m) * 2 + 1];
  __syncthreads();
  int yv = 118 + yf;
  float ar = 0, ai = 0;
  for (int p = 0; p < NP; p++) {
    if (g_wy[p] == yv) {
      int idx = (g_wx[p] * m) & 255;
      float cc = twc[idx], ss = tws[idx];
      float dr = dsr[p], di = dsi[p];
      ar += dr * cc - di * ss;
      ai += dr * ss + di * cc;
    }
  }
  g_R[((size_t)(b * 16 + yf) * 256 + m) * 2] = ar;
  g_R[((size_t)(b * 16 + yf) * 256 + m) * 2 + 1] = ai;
}

// corr[b,n,m] = (1/65536) sum_yf Re[e^{+2pi i (118+yf) n /256} R[b,yf,m]]; add into bufB ch0
__global__ void dft_corr_kernel() {
  int n = blockIdx.x, b = blockIdx.y;
  int m = threadIdx.x;
  __shared__ float twc[256], tws[256];
  float s, c;
  sincosf((float)m * (TWO_PI / 256.f), &s, &c);
  twc[m] = c; tws[m] = s;
  __syncthreads();
  float acc = 0.f;
#pragma unroll
  for (int yf = 0; yf < 16; yf++) {
    int idx = ((118 + yf) * n) & 255;
    float cc = twc[idx], ss = tws[idx];
    float Rr = g_R[((size_t)(b * 16 + yf) * 256 + m) * 2];
    float Ri = g_R[((size_t)(b * 16 + yf) * 256 + m) * 2 + 1];
    acc += cc * Rr - ss * Ri;
  }
  g_bufB[((size_t)b * CC) * HW + (size_t)n * WW + m] += acc * (1.0f / 65536.0f);
}

// ---------------- final 1x1 projection ----------------
__global__ void proj_kernel(const float* __restrict__ wf, const float* __restrict__ bf,
                            float* __restrict__ out) {
  int tid = threadIdx.x;
  __shared__ float wfs[192];
  if (tid < 192) wfs[tid] = wf[tid];
  __syncthreads();
  int P = blockIdx.x * 256 + tid;
  int b = P >> 16;
  int pix = P & 65535;
  const float* src = g_bufA + (size_t)b * CC * HW + pix;
  float a0 = bf[0], a1 = bf[1], a2 = bf[2];
#pragma unroll
  for (int c = 0; c < CC; c++) {
    float v = src[(size_t)c * HW];
    a0 += v * wfs[c];
    a1 += v * wfs[64 + c];
    a2 += v * wfs[128 + c];
  }
  size_t ob = ((size_t)b * 3) * HW + pix;
  out[ob] = a0;
  out[ob + HW] = a1;
  out[ob + 2 * HW] = a2;
}

// ---------------- launch ----------------
extern "C" void kernel_launch(void* const* d_in, const int* in_sizes, int n_in,
                              void* d_out, int out_size) {
  const float* image   = (const float*)d_in[0];
  const float* message = (const float*)d_in[1];
  const float* w0  = (const float*)d_in[2];
  const float* b0  = (const float*)d_in[3];
  const float* g0  = (const float*)d_in[4];
  const float* be0 = (const float*)d_in[5];
  const float* m0  = (const float*)d_in[6];
  const float* v0  = (const float*)d_in[7];
  const float* wk  = (const float*)d_in[8];
  const float* bk  = (const float*)d_in[9];
  const float* gk  = (const float*)d_in[10];
  const float* bek = (const float*)d_in[11];
  const float* mk  = (const float*)d_in[12];
  const float* vk  = (const float*)d_in[13];
  const float* wa  = (const float*)d_in[14];
  const float* ba  = (const float*)d_in[15];
  const float* ga  = (const float*)d_in[16];
  const float* bea = (const float*)d_in[17];
  const float* ma  = (const float*)d_in[18];
  const float* va  = (const float*)d_in[19];
  const float* wf  = (const float*)d_in[20];
  const float* bf  = (const float*)d_in[21];
  float* out = (float*)d_out;

  prep_kernel<<<1, 256>>>(b0, g0, be0, m0, v0, bk, gk, bek, mk, vk, ba, ga, bea, ma, va);

  dim3 cg(64, 4, NB);
  // conv0: image(3) -> bufA
  conv3x3_kernel<<<cg, 256>>>(image, 3, -1, 0, 0, w0, 3, 0, 0, 0);
  // k-layers: 64->64
  conv3x3_kernel<<<cg, 256>>>(nullptr, 0, 0, 64, 1, wk + 0 * 64 * 64 * 9, 64, 0, 1, 0);
  conv3x3_kernel<<<cg, 256>>>(nullptr, 0, 1, 64, 0, wk + 1 * 64 * 64 * 9, 64, 0, 2, 0);
  conv3x3_kernel<<<cg, 256>>>(nullptr, 0, 0, 64, 1, wk + 2 * 64 * 64 * 9, 64, 0, 3, 0);

  // watermark: sparse-frequency DFT correction on bufB channel 0
  dft_rows_kernel<<<dim3(256, NB), 256>>>();
  dft_points_kernel<<<NB, 256>>>(message);
  dft_R_kernel<<<dim3(16, NB), 256>>>();
  dft_corr_kernel<<<dim3(256, NB), 256>>>();

  // message-channel taps + final conv: [bufB(64) | image(3)] -> bufA (weights wa, ic offset 256)
  msgT_kernel<<<dim3(64, NB), 256>>>(message, wa);
  conv3x3_kernel<<<cg, 256>>>(image, 3, 1, 64, 0, wa, 323, 256, 4, 1);

  // 1x1 projection -> out
  proj_kernel<<<NB * HW / 256, 256>>>(wf, bf, out);
}

// round 3
// speedup vs baseline: 1.6794x; 1.6791x over previous
#include <cuda_runtime.h>
#include <math.h>
#include <stdint.h>

#define HH 256
#define WW 256
#define HW 65536
#define NB 16
#define CC 64
#define LL 256
#define NP 256   // watermark points (all in channel 0)

// ---------------- scratch (no allocations allowed) ----------------
__device__ float g_bufA[NB * CC * HW];   // 268 MB
__device__ float g_bufB[NB * CC * HW];   // 268 MB
__device__ float g_H[NB * 21 * 256 * 2]; // column DFT at 21 distinct x-freqs
__device__ float g_d[NB * NP * 2];       // delta at watermark points
__device__ float g_R[NB * 16 * 256 * 2]; // per-row inverse partial
__device__ float g_T[NB * CC * 9];       // msg-channel conv taps
__device__ float g_scale[5 * CC];
__device__ float g_bias[5 * CC];
__device__ int   g_wy[NP];
__device__ int   g_wx[NP];

#define TWO_PI 6.283185307179586f

// packed fp32x2 helpers (Blackwell FFMA2 path)
#define FMA_F32X2(d, a, b) \
  asm("fma.rn.f32x2 %0, %1, %2, %0;" : "+l"(d) : "l"(a), "l"(b))
#define ADD_F32X2_(d, a, b) \
  asm("add.rn.f32x2 %0, %1, %2;" : "=l"(d) : "l"(a), "l"(b))
#define PACK_DUP(out, v) \
  asm("mov.b64 %0, {%1, %1};" : "=l"(out) : "r"(__float_as_uint(v)))
#define UNPACK_2(lo, hi, in) \
  asm("mov.b64 {%0, %1}, %2;" : "=r"(lo), "=r"(hi) : "l"(in))

// ---------------- prep: fold BN, watermark indices ----------------
__global__ void prep_kernel(const float* b0, const float* g0, const float* be0,
                            const float* m0, const float* v0,
                            const float* bk, const float* gk, const float* bek,
                            const float* mk, const float* vk,
                            const float* ba, const float* ga, const float* bea,
                            const float* ma, const float* va) {
  int c = threadIdx.x;
  const float EPS = 1e-5f;
  if (c < CC) {
    float s = g0[c] * rsqrtf(v0[c] + EPS);
    g_scale[c] = s;
    g_bias[c] = be0[c] + (b0[c] - m0[c]) * s;
    for (int t = 0; t < 3; t++) {
      float st = gk[t * CC + c] * rsqrtf(vk[t * CC + c] + EPS);
      g_scale[(1 + t) * CC + c] = st;
      g_bias[(1 + t) * CC + c] = bek[t * CC + c] + (bk[t * CC + c] - mk[t * CC + c]) * st;
    }
    float sa = ga[c] * rsqrtf(va[c] + EPS);
    g_scale[4 * CC + c] = sa;
    g_bias[4 * CC + c] = bea[c] + (ba[c] - ma[c]) * sa;
  }
  if (c == 0) {
    int cnt = 0;
    for (int ch = 0; ch < CC && cnt < NP; ch++)
      for (int i = -10; i <= 10 && cnt < NP; i++)
        for (int j = -10; j <= 10; j++) {
          if (cnt >= NP) break;
          int y = 128 + i, x = 128 + j;
          if (y >= 0 && y < HH && x >= 0 && x < WW && (i * i + j * j <= 100)) {
            g_wy[cnt] = y; g_wx[cnt] = x; cnt++;
          }
        }
  }
}

// ---------------- msg-channel conv taps: T[b,o,kh,kw] ----------------
__global__ void msgT_kernel(const float* __restrict__ message,
                            const float* __restrict__ wa) {
  int o = blockIdx.x, b = blockIdx.y;
  int c = threadIdx.x;
  __shared__ float red[8];
  float mv = message[b * LL + c];
  const float* wp = wa + ((size_t)o * 323 + c) * 9;
  for (int t = 0; t < 9; t++) {
    float v = mv * wp[t];
#pragma unroll
    for (int off = 16; off > 0; off >>= 1) v += __shfl_down_sync(0xffffffffu, v, off);
    if ((c & 31) == 0) red[c >> 5] = v;
    __syncthreads();
    if (c == 0) {
      float s = 0;
      for (int w = 0; w < 8; w++) s += red[w];
      g_T[(b * CC + o) * 9 + t] = s;
    }
    __syncthreads();
  }
}

// ---------------- main tiled 3x3 conv + BN + ReLU ----------------
// block: 256 threads, 32x32 spatial tile, 16 output channels.
// FFMA2 (f32x2) over output-channel pairs; double-buffered tile staging.
__launch_bounds__(256, 2)
__global__ void conv3x3_kernel(const float* __restrict__ ext_in, int extC,
                               int bufSrc, int bufC, int bufDst,
                               const float* __restrict__ Wt, int CW, int ic0,
                               int layer, int use_msg) {
  __shared__ __align__(16) float w_s[67 * 144];
  __shared__ __align__(16) float tile[2][34 * 34 + 2];
  __shared__ __align__(16) float T_s[16 * 9];  // layout [tap][oc16]

  float* bufs[2] = {g_bufA, g_bufB};
  const float* bsrc = (bufSrc >= 0) ? bufs[bufSrc] : nullptr;
  float* out = bufs[bufDst];

  int tid = threadIdx.x;
  int ocg = blockIdx.x, tileId = blockIdx.y, b = blockIdx.z;
  int y0 = (tileId >> 3) << 5, x0 = (tileId & 7) << 5;
  int Ctot = bufC + extC;

  // stage all weights for this oc-group: layout [c][tap][oc16]
  int Wstride = CW * 9;
  for (int idx = tid; idx < Ctot * 144; idx += 256) {
    int c = idx / 144;
    int rem = idx - c * 144;
    int t = rem >> 4;
    int oc = rem & 15;
    w_s[idx] = Wt[(size_t)(ocg * 16 + oc) * Wstride + (ic0 + c) * 9 + t];
  }
  if (use_msg && tid < 144)  // transpose to [tap][oc]
    T_s[(tid % 9) * 16 + (tid / 9)] = g_T[(b * CC + ocg * 16 + (tid / 9)) * 9 + (tid % 9)];

  int tx = tid & 31, ty = tid >> 5;
  unsigned long long acc2[4][8];
#pragma unroll
  for (int k = 0; k < 4; k++)
#pragma unroll
    for (int o = 0; o < 8; o++) acc2[k][o] = 0ull;

  // stage channel 0 tile into buffer 0
  {
    const float* src0 = (0 < bufC)
        ? (bsrc + ((size_t)(b * bufC)) * HW)
        : (ext_in + ((size_t)(b * extC)) * HW);
    for (int idx = tid; idx < 34 * 34; idx += 256) {
      int r = idx / 34, cl = idx - r * 34;
      int gy = y0 + r - 1, gx = x0 + cl - 1;
      float v = 0.f;
      if (gy >= 0 && gy < HH && gx >= 0 && gx < WW) v = src0[gy * WW + gx];
      tile[0][idx] = v;
    }
  }
  __syncthreads();

  // message-channel contribution (constant per pixel except borders)
  if (use_msg) {
#pragma unroll
    for (int kh = 0; kh < 3; kh++) {
#pragma unroll
      for (int kw = 0; kw < 3; kw++) {
        int t = kh * 3 + kw;
        const unsigned long long* tp = (const unsigned long long*)(T_s + t * 16);
        unsigned long long tpr[8];
#pragma unroll
        for (int o = 0; o < 8; o++) tpr[o] = tp[o];
#pragma unroll
        for (int k = 0; k < 4; k++) {
          int iy = y0 + ty + 8 * k + kh - 1;
          int ix = x0 + tx + kw - 1;
          if (iy >= 0 && iy < HH && ix >= 0 && ix < WW) {
#pragma unroll
            for (int o = 0; o < 8; o++) ADD_F32X2_(acc2[k][o], acc2[k][o], tpr[o]);
          }
        }
      }
    }
  }

  for (int c = 0; c < Ctot; c++) {
    int cur = c & 1, nxt = cur ^ 1;

    // prefetch next channel tile into registers (hidden under compute)
    float pre[5];
    bool havePre = (c + 1 < Ctot);
    if (havePre) {
      int cn = c + 1;
      const float* srcn = (cn < bufC)
          ? (bsrc + ((size_t)(b * bufC + cn)) * HW)
          : (ext_in + ((size_t)(b * extC + (cn - bufC))) * HW);
#pragma unroll
      for (int i = 0; i < 5; i++) {
        int idx = tid + 256 * i;
        float v = 0.f;
        if (idx < 34 * 34) {
          int r = idx / 34, cl = idx - r * 34;
          int gy = y0 + r - 1, gx = x0 + cl - 1;
          if (gy >= 0 && gy < HH && gx >= 0 && gx < WW) v = srcn[gy * WW + gx];
        }
        pre[i] = v;
      }
    }

    // compute on current tile
    const float* wc = w_s + c * 144;
    const float* trow = tile[cur] + ty * 34 + tx;
#pragma unroll
    for (int kh = 0; kh < 3; kh++) {
#pragma unroll
      for (int kw = 0; kw < 3; kw++) {
        int t = kh * 3 + kw;
        const unsigned long long* wp2 = (const unsigned long long*)(wc + t * 16);
        unsigned long long wp[8];
#pragma unroll
        for (int o = 0; o < 8; o += 2) {  // LDS.128 -> 2 pairs
          ulonglong2 q = *(const ulonglong2*)(wp2 + o);
          wp[o] = q.x; wp[o + 1] = q.y;
        }
#pragma unroll
        for (int k = 0; k < 4; k++) {
          float v = trow[(8 * k + kh) * 34 + kw];
          unsigned long long vv;
          PACK_DUP(vv, v);
          FMA_F32X2(acc2[k][0], vv, wp[0]);
          FMA_F32X2(acc2[k][1], vv, wp[1]);
          FMA_F32X2(acc2[k][2], vv, wp[2]);
          FMA_F32X2(acc2[k][3], vv, wp[3]);
          FMA_F32X2(acc2[k][4], vv, wp[4]);
          FMA_F32X2(acc2[k][5], vv, wp[5]);
          FMA_F32X2(acc2[k][6], vv, wp[6]);
          FMA_F32X2(acc2[k][7], vv, wp[7]);
        }
      }
    }

    // store prefetched tile, single barrier per channel
    if (havePre) {
#pragma unroll
      for (int i = 0; i < 5; i++) {
        int idx = tid + 256 * i;
        if (idx < 34 * 34) tile[nxt][idx] = pre[i];
      }
    }
    __syncthreads();
  }

  const float* scp = g_scale + layer * CC + ocg * 16;
  const float* bip = g_bias + layer * CC + ocg * 16;
#pragma unroll
  for (int k = 0; k < 4; k++) {
    int y = y0 + ty + 8 * k;
    size_t base = ((size_t)(b * CC + ocg * 16)) * HW + (size_t)y * WW + x0 + tx;
#pragma unroll
    for (int o = 0; o < 8; o++) {
      unsigned lo, hi;
      UNPACK_2(lo, hi, acc2[k][o]);
      float r0 = __uint_as_float(lo) * scp[2 * o] + bip[2 * o];
      float r1 = __uint_as_float(hi) * scp[2 * o + 1] + bip[2 * o + 1];
      out[base + (size_t)(2 * o) * HW] = r0 > 0.f ? r0 : 0.f;
      out[base + (size_t)(2 * o + 1) * HW] = r1 > 0.f ? r1 : 0.f;
    }
  }
}

// ---------------- sparse-frequency DFT chain (channel 0 of g_bufB) ----------
// H[b,f,n] = sum_m x[b,0,n,m] * e^{-2pi i (118+f) m / 256}
__global__ void dft_rows_kernel() {
  int n = blockIdx.x, b = blockIdx.y;
  int m = threadIdx.x;
  __shared__ float row[256], twc[256], tws[256], red[16];
  float s, c;
  sincosf((float)m * (TWO_PI / 256.f), &s, &c);
  twc[m] = c; tws[m] = s;
  row[m] = g_bufB[((size_t)b * CC) * HW + (size_t)n * WW + m];
  __syncthreads();
  float x = row[m];
  int lane = m & 31, wid = m >> 5;
  for (int f = 0; f < 21; f++) {
    int idx = ((118 + f) * m) & 255;
    float pr = x * twc[idx];
    float pi = -x * tws[idx];
#pragma unroll
    for (int off = 16; off > 0; off >>= 1) {
      pr += __shfl_down_sync(0xffffffffu, pr, off);
      pi += __shfl_down_sync(0xffffffffu, pi, off);
    }
    if (lane == 0) { red[wid] = pr; red[8 + wid] = pi; }
    __syncthreads();
    if (m == 0) {
      float sr = 0, si = 0;
      for (int w = 0; w < 8; w++) { sr += red[w]; si += red[8 + w]; }
      g_H[((size_t)(b * 21 + f) * 256 + n) * 2] = sr;
      g_H[((size_t)(b * 21 + f) * 256 + n) * 2 + 1] = si;
    }
    __syncthreads();
  }
}

// F[b,p] = sum_n e^{-2pi i y_p n/256} H[b, f(x_p), n];  d = (msg + i msg) - F
__global__ void dft_points_kernel(const float* __restrict__ message) {
  int b = blockIdx.x;
  int p = threadIdx.x;
  __shared__ float twc[256], tws[256];
  float s, c;
  sincosf((float)p * (TWO_PI / 256.f), &s, &c);
  twc[p] = c; tws[p] = s;
  __syncthreads();
  int yp = g_wy[p], xp = g_wx[p];
  int f = xp - 118;
  const float* Hp = g_H + (size_t)(b * 21 + f) * 512;
  float Fr = 0, Fi = 0;
  for (int n = 0; n < 256; n++) {
    int idx = (yp * n) & 255;
    float cc = twc[idx], ss = tws[idx];
    float hr = Hp[n * 2], hi = Hp[n * 2 + 1];
    Fr += hr * cc + hi * ss;   // e^{-i t} * H
    Fi += hi * cc - hr * ss;
  }
  float mv = message[b * LL + p];
  g_d[(b * NP + p) * 2] = mv - Fr;
  g_d[(b * NP + p) * 2 + 1] = mv - Fi;
}

// R[b,yf,m] = sum_{p: y_p = 118+yf} d_p e^{+2pi i x_p m/256}
__global__ void dft_R_kernel() {
  int yf = blockIdx.x, b = blockIdx.y;
  int m = threadIdx.x;
  __shared__ float twc[256], tws[256], dsr[256], dsi[256];
  float s, c;
  sincosf((float)m * (TWO_PI / 256.f), &s, &c);
  twc[m] = c; tws[m] = s;
  dsr[m] = g_d[(b * NP + m) * 2];
  dsi[m] = g_d[(b * NP + m) * 2 + 1];
  __syncthreads();
  int yv = 118 + yf;
  float ar = 0, ai = 0;
  for (int p = 0; p < NP; p++) {
    if (g_wy[p] == yv) {
      int idx = (g_wx[p] * m) & 255;
      float cc = twc[idx], ss = tws[idx];
      float dr = dsr[p], di = dsi[p];
      ar += dr * cc - di * ss;
      ai += dr * ss + di * cc;
    }
  }
  g_R[((size_t)(b * 16 + yf) * 256 + m) * 2] = ar;
  g_R[((size_t)(b * 16 + yf) * 256 + m) * 2 + 1] = ai;
}

// corr[b,n,m] = (1/65536) sum_yf Re[e^{+2pi i (118+yf) n /256} R[b,yf,m]]; add into bufB ch0
__global__ void dft_corr_kernel() {
  int n = blockIdx.x, b = blockIdx.y;
  int m = threadIdx.x;
  __shared__ float twc[256], tws[256];
  float s, c;
  sincosf((float)m * (TWO_PI / 256.f), &s, &c);
  twc[m] = c; tws[m] = s;
  __syncthreads();
  float acc = 0.f;
#pragma unroll
  for (int yf = 0; yf < 16; yf++) {
    int idx = ((118 + yf) * n) & 255;
    float cc = twc[idx], ss = tws[idx];
    float Rr = g_R[((size_t)(b * 16 + yf) * 256 + m) * 2];
    float Ri = g_R[((size_t)(b * 16 + yf) * 256 + m) * 2 + 1];
    acc += cc * Rr - ss * Ri;
  }
  g_bufB[((size_t)b * CC) * HW + (size_t)n * WW + m] += acc * (1.0f / 65536.0f);
}

// ---------------- final 1x1 projection ----------------
__global__ void proj_kernel(const float* __restrict__ wf, const float* __restrict__ bf,
                            float* __restrict__ out) {
  int tid = threadIdx.x;
  __shared__ float wfs[192];
  if (tid < 192) wfs[tid] = wf[tid];
  __syncthreads();
  int P = blockIdx.x * 256 + tid;
  int b = P >> 16;
  int pix = P & 65535;
  const float* src = g_bufA + (size_t)b * CC * HW + pix;
  float a0 = bf[0], a1 = bf[1], a2 = bf[2];
#pragma unroll
  for (int c = 0; c < CC; c++) {
    float v = src[(size_t)c * HW];
    a0 += v * wfs[c];
    a1 += v * wfs[64 + c];
    a2 += v * wfs[128 + c];
  }
  size_t ob = ((size_t)b * 3) * HW + pix;
  out[ob] = a0;
  out[ob + HW] = a1;
  out[ob + 2 * HW] = a2;
}

// ---------------- launch ----------------
extern "C" void kernel_launch(void* const* d_in, const int* in_sizes, int n_in,
                              void* d_out, int out_size) {
  const float* image   = (const float*)d_in[0];
  const float* message = (const float*)d_in[1];
  const float* w0  = (const float*)d_in[2];
  const float* b0  = (const float*)d_in[3];
  const float* g0  = (const float*)d_in[4];
  const float* be0 = (const float*)d_in[5];
  const float* m0  = (const float*)d_in[6];
  const float* v0  = (const float*)d_in[7];
  const float* wk  = (const float*)d_in[8];
  const float* bk  = (const float*)d_in[9];
  const float* gk  = (const float*)d_in[10];
  const float* bek = (const float*)d_in[11];
  const float* mk  = (const float*)d_in[12];
  const float* vk  = (const float*)d_in[13];
  const float* wa  = (const float*)d_in[14];
  const float* ba  = (const float*)d_in[15];
  const float* ga  = (const float*)d_in[16];
  const float* bea = (const float*)d_in[17];
  const float* ma  = (const float*)d_in[18];
  const float* va  = (const float*)d_in[19];
  const float* wf  = (const float*)d_in[20];
  const float* bf  = (const float*)d_in[21];
  float* out = (float*)d_out;

  prep_kernel<<<1, 256>>>(b0, g0, be0, m0, v0, bk, gk, bek, mk, vk, ba, ga, bea, ma, va);

  dim3 cg(4, 64, NB);  // ocg fastest -> 4 blocks sharing a tile run together (L2 reuse)
  // conv0: image(3) -> bufA
  conv3x3_kernel<<<cg, 256>>>(image, 3, -1, 0, 0, w0, 3, 0, 0, 0);
  // k-layers: 64->64
  conv3x3_kernel<<<cg, 256>>>(nullptr, 0, 0, 64, 1, wk + 0 * 64 * 64 * 9, 64, 0, 1, 0);
  conv3x3_kernel<<<cg, 256>>>(nullptr, 0, 1, 64, 0, wk + 1 * 64 * 64 * 9, 64, 0, 2, 0);
  conv3x3_kernel<<<cg, 256>>>(nullptr, 0, 0, 64, 1, wk + 2 * 64 * 64 * 9, 64, 0, 3, 0);

  // watermark: sparse-frequency DFT correction on bufB channel 0
  dft_rows_kernel<<<dim3(256, NB), 256>>>();
  dft_points_kernel<<<NB, 256>>>(message);
  dft_R_kernel<<<dim3(16, NB), 256>>>();
  dft_corr_kernel<<<dim3(256, NB), 256>>>();

  // message-channel taps + final conv: [bufB(64) | image(3)] -> bufA (weights wa, ic offset 256)
  msgT_kernel<<<dim3(64, NB), 256>>>(message, wa);
  conv3x3_kernel<<<cg, 256>>>(image, 3, 1, 64, 0, wa, 323, 256, 4, 1);

  // 1x1 projection -> out
  proj_kernel<<<NB * HW / 256, 256>>>(wf, bf, out);
}

// round 6
// speedup vs baseline: 3.3066x; 1.9689x over previous
#include <cuda_runtime.h>
#include <cuda_bf16.h>
#include <math.h>
#include <stdint.h>

#define HH 256
#define WW 256
#define HW 65536
#define NB 16
#define CC 64
#define LL 256
#define NP 256

__device__ __nv_bfloat16 g_aH0[NB * HW * 64];
__device__ __nv_bfloat16 g_aL0[NB * HW * 64];
__device__ __nv_bfloat16 g_aH1[NB * HW * 64];
__device__ __nv_bfloat16 g_aL1[NB * HW * 64];
__device__ float g_extra[NB * HW * 64];          // layer-4 img+msg side field (raw)
__device__ __nv_bfloat16 g_wH[4 * 9 * 64 * 64];  // [slot][tap][oc][ic] hi
__device__ __nv_bfloat16 g_wL[4 * 9 * 64 * 64];  // lo
__device__ float g_H[NB * 21 * 256 * 2];
__device__ float g_d[NB * NP * 2];
__device__ float g_R[NB * 16 * 256 * 2];
__device__ float g_T[NB * CC * 9];
__device__ float g_scale[5 * CC];
__device__ float g_bias[5 * CC];
__device__ int   g_wy[NP];
__device__ int   g_wx[NP];

#define TWO_PI 6.283185307179586f

// ---- scalar packed-fp32 helpers ----
#define FMA_F32X2(d, a, b) \
  asm("fma.rn.f32x2 %0, %1, %2, %0;" : "+l"(d) : "l"(a), "l"(b))
#define ADD_F32X2_(d, a, b) \
  asm("add.rn.f32x2 %0, %1, %2;" : "=l"(d) : "l"(a), "l"(b))
#define PACK_DUP(out, v) \
  asm("mov.b64 %0, {%1, %1};" : "=l"(out) : "r"(__float_as_uint(v)))
#define UNPACK_2(lo, hi, in) \
  asm("mov.b64 {%0, %1}, %2;" : "=r"(lo), "=r"(hi) : "l"(in))

// ---- HMMA helpers (baseline PTX, no sm_103a features) ----
__device__ __forceinline__ uint32_t smem_u32(const void* p) {
  uint32_t a;
  asm("{ .reg .u64 t; cvta.to.shared.u64 t, %1; cvt.u32.u64 %0, t; }" : "=r"(a) : "l"(p));
  return a;
}
#define LDM4(r, addr) \
  asm volatile("ldmatrix.sync.aligned.m8n8.x4.shared.b16 {%0,%1,%2,%3}, [%4];" \
    : "=r"((r)[0]), "=r"((r)[1]), "=r"((r)[2]), "=r"((r)[3]) : "r"(addr))
#define MMA16816(d, a, b0, b1) \
  asm volatile("mma.sync.aligned.m16n8k16.row.col.f32.bf16.bf16.f32 " \
    "{%0,%1,%2,%3}, {%4,%5,%6,%7}, {%8,%9}, {%0,%1,%2,%3};" \
    : "+f"((d)[0]), "+f"((d)[1]), "+f"((d)[2]), "+f"((d)[3]) \
    : "r"((a)[0]), "r"((a)[1]), "r"((a)[2]), "r"((a)[3]), "r"(b0), "r"(b1))

// smem layout for conv_mma
#define ACT_H 1536
#define ACT_L 27456
#define WGT_H 53376
#define WGT_L 136320
#define SMEM_MMA_TOTAL 219264
#define PST 144   // padded 16B-aligned row stride (conflict-free ldmatrix)

__global__ void prep_kernel(const float* b0, const float* g0, const float* be0,
                            const float* m0, const float* v0,
                            const float* bk, const float* gk, const float* bek,
                            const float* mk, const float* vk,
                            const float* ba, const float* ga, const float* bea,
                            const float* ma, const float* va) {
  int c = threadIdx.x;
  const float EPS = 1e-5f;
  if (c < CC) {
    float s = g0[c] * rsqrtf(v0[c] + EPS);
    g_scale[c] = s;
    g_bias[c] = be0[c] + (b0[c] - m0[c]) * s;
    for (int t = 0; t < 3; t++) {
      float st = gk[t * CC + c] * rsqrtf(vk[t * CC + c] + EPS);
      g_scale[(1 + t) * CC + c] = st;
      g_bias[(1 + t) * CC + c] = bek[t * CC + c] + (bk[t * CC + c] - mk[t * CC + c]) * st;
    }
    float sa = ga[c] * rsqrtf(va[c] + EPS);
    g_scale[4 * CC + c] = sa;
    g_bias[4 * CC + c] = bea[c] + (ba[c] - ma[c]) * sa;
  }
  if (c == 0) {
    int cnt = 0;
    for (int ch = 0; ch < CC && cnt < NP; ch++)
      for (int i = -10; i <= 10 && cnt < NP; i++)
        for (int j = -10; j <= 10; j++) {
          if (cnt >= NP) break;
          int y = 128 + i, x = 128 + j;
          if (y >= 0 && y < HH && x >= 0 && x < WW && (i * i + j * j <= 100)) {
            g_wy[cnt] = y; g_wx[cnt] = x; cnt++;
          }
        }
  }
}

// split weights to bf16 hi/lo, layout [slot][tap][oc][ic]
__global__ void prep_w_kernel(const float* __restrict__ wk, const float* __restrict__ wa) {
  int i = blockIdx.x * 256 + threadIdx.x;
  int l = i / 36864;
  int rem = i - l * 36864;
  int t = rem / 4096;
  int r2 = rem & 4095;
  int oc = r2 >> 6, ic = r2 & 63;
  float w = (l < 3) ? wk[(((size_t)l * 64 + oc) * 64 + ic) * 9 + t]
                    : wa[((size_t)oc * 323 + 256 + ic) * 9 + t];
  __nv_bfloat16 h = __float2bfloat16(w);
  g_wH[i] = h;
  g_wL[i] = __float2bfloat16(w - __bfloat162float(h));
}

__global__ void msgT_kernel(const float* __restrict__ message,
                            const float* __restrict__ wa) {
  int o = blockIdx.x, b = blockIdx.y;
  int c = threadIdx.x;
  __shared__ float red[8];
  float mv = message[b * LL + c];
  const float* wp = wa + ((size_t)o * 323 + c) * 9;
  for (int t = 0; t < 9; t++) {
    float v = mv * wp[t];
#pragma unroll
    for (int off = 16; off > 0; off >>= 1) v += __shfl_down_sync(0xffffffffu, v, off);
    if ((c & 31) == 0) red[c >> 5] = v;
    __syncthreads();
    if (c == 0) {
      float s = 0;
      for (int w2 = 0; w2 < 8; w2++) s += red[w2];
      g_T[(b * CC + o) * 9 + t] = s;
    }
    __syncthreads();
  }
}

// scalar FFMA2 conv over 3 channels. mode 0: BN+ReLU -> g_aH0/g_aL0. mode 1: raw fp32 -> g_extra.
__launch_bounds__(256, 2)
__global__ void conv3_scalar_kernel(const float* __restrict__ ext_in,
                                    const float* __restrict__ Wt, int CW, int ic0,
                                    int layer, int use_msg, int mode) {
  __shared__ __align__(16) float w_s[3 * 144];
  __shared__ __align__(16) float tile[2][34 * 34 + 2];
  __shared__ __align__(16) float T_s[16 * 9];

  int tid = threadIdx.x;
  int ocg = blockIdx.x, tileId = blockIdx.y, b = blockIdx.z;
  int y0 = (tileId >> 3) << 5, x0 = (tileId & 7) << 5;

  int Wstride = CW * 9;
  for (int idx = tid; idx < 3 * 144; idx += 256) {
    int c = idx / 144;
    int rem = idx - c * 144;
    int t = rem >> 4;
    int oc = rem & 15;
    w_s[idx] = Wt[(size_t)(ocg * 16 + oc) * Wstride + (ic0 + c) * 9 + t];
  }
  if (use_msg && tid < 144)
    T_s[(tid % 9) * 16 + (tid / 9)] = g_T[(b * CC + ocg * 16 + (tid / 9)) * 9 + (tid % 9)];

  int tx = tid & 31, ty = tid >> 5;
  unsigned long long acc2[4][8];
#pragma unroll
  for (int k = 0; k < 4; k++)
#pragma unroll
    for (int o = 0; o < 8; o++) acc2[k][o] = 0ull;

  {
    const float* src0 = ext_in + ((size_t)(b * 3)) * HW;
    for (int idx = tid; idx < 34 * 34; idx += 256) {
      int r = idx / 34, cl = idx - r * 34;
      int gy = y0 + r - 1, gx = x0 + cl - 1;
      float v = 0.f;
      if (gy >= 0 && gy < HH && gx >= 0 && gx < WW) v = src0[gy * WW + gx];
      tile[0][idx] = v;
    }
  }
  __syncthreads();

  if (use_msg) {
#pragma unroll
    for (int kh = 0; kh < 3; kh++) {
#pragma unroll
      for (int kw = 0; kw < 3; kw++) {
        int t = kh * 3 + kw;
        const unsigned long long* tp = (const unsigned long long*)(T_s + t * 16);
        unsigned long long tpr[8];
#pragma unroll
        for (int o = 0; o < 8; o++) tpr[o] = tp[o];
#pragma unroll
        for (int k = 0; k < 4; k++) {
          int iy = y0 + ty + 8 * k + kh - 1;
          int ix = x0 + tx + kw - 1;
          if (iy >= 0 && iy < HH && ix >= 0 && ix < WW) {
#pragma unroll
            for (int o = 0; o < 8; o++) ADD_F32X2_(acc2[k][o], acc2[k][o], tpr[o]);
          }
        }
      }
    }
  }

  for (int c = 0; c < 3; c++) {
    int cur = c & 1, nxt = cur ^ 1;
    float pre[5];
    bool havePre = (c + 1 < 3);
    if (havePre) {
      const float* srcn = ext_in + ((size_t)(b * 3 + c + 1)) * HW;
#pragma unroll
      for (int i = 0; i < 5; i++) {
        int idx = tid + 256 * i;
        float v = 0.f;
        if (idx < 34 * 34) {
          int r = idx / 34, cl = idx - r * 34;
          int gy = y0 + r - 1, gx = x0 + cl - 1;
          if (gy >= 0 && gy < HH && gx >= 0 && gx < WW) v = srcn[gy * WW + gx];
        }
        pre[i] = v;
      }
    }
    const float* wc = w_s + c * 144;
    const float* trow = tile[cur] + ty * 34 + tx;
#pragma unroll
    for (int kh = 0; kh < 3; kh++) {
#pragma unroll
      for (int kw = 0; kw < 3; kw++) {
        int t = kh * 3 + kw;
        const unsigned long long* wp2 = (const unsigned long long*)(wc + t * 16);
        unsigned long long wp[8];
#pragma unroll
        for (int o = 0; o < 8; o += 2) {
          ulonglong2 q = *(const ulonglong2*)(wp2 + o);
          wp[o] = q.x; wp[o + 1] = q.y;
        }
#pragma unroll
        for (int k = 0; k < 4; k++) {
          float v = trow[(8 * k + kh) * 34 + kw];
          unsigned long long vv;
          PACK_DUP(vv, v);
#pragma unroll
          for (int o = 0; o < 8; o++) FMA_F32X2(acc2[k][o], vv, wp[o]);
        }
      }
    }
    if (havePre) {
#pragma unroll
      for (int i = 0; i < 5; i++) {
        int idx = tid + 256 * i;
        if (idx < 34 * 34) tile[nxt][idx] = pre[i];
      }
    }
    __syncthreads();
  }

  const float* scp = g_scale + layer * CC + ocg * 16;
  const float* bip = g_bias + layer * CC + ocg * 16;
#pragma unroll
  for (int k = 0; k < 4; k++) {
    int y = y0 + ty + 8 * k;
    size_t pixb = ((size_t)b * HW + (size_t)y * WW + x0 + tx) * 64 + ocg * 16;
    float r[16];
#pragma unroll
    for (int o = 0; o < 8; o++) {
      unsigned lo, hi;
      UNPACK_2(lo, hi, acc2[k][o]);
      r[2 * o] = __uint_as_float(lo);
      r[2 * o + 1] = __uint_as_float(hi);
    }
    if (mode == 0) {
      __nv_bfloat16 hb[16], lb[16];
#pragma unroll
      for (int o = 0; o < 16; o++) {
        float v = r[o] * scp[o] + bip[o];
        v = v > 0.f ? v : 0.f;
        __nv_bfloat16 h = __float2bfloat16(v);
        hb[o] = h;
        lb[o] = __float2bfloat16(v - __bfloat162float(h));
      }
      uint4* dh = (uint4*)(g_aH0 + pixb);
      uint4* dl = (uint4*)(g_aL0 + pixb);
      dh[0] = ((uint4*)hb)[0]; dh[1] = ((uint4*)hb)[1];
      dl[0] = ((uint4*)lb)[0]; dl[1] = ((uint4*)lb)[1];
    } else {
      uint4* df = (uint4*)(g_extra + pixb);
#pragma unroll
      for (int q = 0; q < 4; q++) df[q] = ((uint4*)r)[q];
    }
  }
}

// ---------------- HMMA bf16-split implicit-GEMM 3x3 conv, 64ic->64oc -------
// CTA: 256 thr, tile 8 rows x 16 cols pixels (m = c*8 + r), loops 4 y-tiles.
__launch_bounds__(256, 1)
__global__ void conv_mma_kernel(int srcSel, int wslot, int layer,
                                int use_extra, int do_proj,
                                const float* __restrict__ wf,
                                const float* __restrict__ bf,
                                float* __restrict__ out) {
  extern __shared__ __align__(16) char smem[];
  float* sc_s = (float*)(smem + 0);
  float* bi_s = (float*)(smem + 256);
  float* wf_s = (float*)(smem + 512);

  int tid = threadIdx.x, w = tid >> 5, lane = tid & 31;
  int tileX = blockIdx.x * 16, b = blockIdx.z;

  const __nv_bfloat16* inH = srcSel ? g_aH1 : g_aH0;
  const __nv_bfloat16* inL = srcSel ? g_aL1 : g_aL0;
  __nv_bfloat16* outH = srcSel ? g_aH0 : g_aH1;
  __nv_bfloat16* outL = srcSel ? g_aL0 : g_aL1;
  const __nv_bfloat16* wHs = g_wH + wslot * 36864;
  const __nv_bfloat16* wLs = g_wL + wslot * 36864;

  // stage weights [tap][oc][ic] with 144B-padded oc rows (both halves), once
  for (int idx = tid; idx < 9216; idx += 256) {
    int half = idx >= 4608;
    int i = half ? idx - 4608 : idx;
    int t = i >> 9;
    int oc = (i >> 3) & 63;
    int ich = i & 7;
    uint4 v = *(const uint4*)((half ? wLs : wHs) + ((size_t)(t * 64 + oc) * 64 + ich * 8));
    *(uint4*)(smem + (half ? WGT_L : WGT_H) + t * 9216 + oc * PST + ich * 16) = v;
  }
  if (tid < 64) { sc_s[tid] = g_scale[layer * CC + tid]; bi_s[tid] = g_bias[layer * CC + tid]; }
  if (do_proj && tid >= 64 && tid < 256) wf_s[tid - 64] = wf[tid - 64];

  uint32_t sb = smem_u32(smem);
  // per-lane ldmatrix bases
  int mL = lane & 15;
  int rL = mL & 7, cL = w * 2 + (mL >> 3);
  uint32_t baseA = (uint32_t)((rL * 18 + cL) * PST + (lane >> 4) * 16);
  uint32_t baseB = (uint32_t)((lane & 7) * PST + ((lane >> 3) & 1) * 16 + (lane >> 4) * (8 * PST));
  int g = lane >> 2, t4 = lane & 3;

  for (int yt = 0; yt < 4; yt++) {
    int tileY = (blockIdx.y * 4 + yt) * 8;
    __syncthreads();  // smem safe to overwrite (also covers weight staging, yt=0)

    // stage activation tile: 2 halves x 10 rows x 18 cols x 8 ch-chunks
    for (int idx = tid; idx < 2880; idx += 256) {
      int half = idx >= 1440;
      int i = half ? idx - 1440 : idx;
      int r10 = i / 144;
      int rem = i - r10 * 144;
      int c18 = rem >> 3, och = rem & 7;
      int gy = tileY - 1 + r10, gx = tileX - 1 + c18;
      uint4 v = make_uint4(0, 0, 0, 0);
      if (gy >= 0 && gy < HH && gx >= 0 && gx < WW)
        v = *(const uint4*)((half ? inL : inH) + (((size_t)b * HW + (size_t)gy * WW + gx) * 64 + och * 8));
      *(uint4*)(smem + (half ? ACT_L : ACT_H) + (r10 * 18 + c18) * PST + och * 16) = v;
    }
    __syncthreads();

    float dacc[8][4];
#pragma unroll
    for (int nb = 0; nb < 8; nb++)
#pragma unroll
      for (int q = 0; q < 4; q++) dacc[nb][q] = 0.f;

    for (int t = 0; t < 9; t++) {
      int toff = ((t / 3) * 18 + (t % 3)) * PST;
      uint32_t aH_t = sb + ACT_H + baseA + toff;
      uint32_t aL_t = sb + ACT_L + baseA + toff;
      uint32_t wH_t = sb + WGT_H + t * 9216 + baseB;
      uint32_t wL_t = sb + WGT_L + t * 9216 + baseB;
#pragma unroll
      for (int kb = 0; kb < 4; kb++) {
        uint32_t ah[4], al[4];
        LDM4(ah, aH_t + kb * 32);
        LDM4(al, aL_t + kb * 32);
#pragma unroll
        for (int j = 0; j < 4; j++) {
          uint32_t bh[4], bl[4];
          LDM4(bh, wH_t + j * 2304 + kb * 32);
          LDM4(bl, wL_t + j * 2304 + kb * 32);
          MMA16816(dacc[2 * j], ah, bh[0], bh[1]);
          MMA16816(dacc[2 * j + 1], ah, bh[2], bh[3]);
          MMA16816(dacc[2 * j], al, bh[0], bh[1]);
          MMA16816(dacc[2 * j + 1], al, bh[2], bh[3]);
          MMA16816(dacc[2 * j], ah, bl[0], bl[1]);
          MMA16816(dacc[2 * j + 1], ah, bl[2], bl[3]);
        }
      }
    }

    // epilogue: thread owns rows g, g+8 of warp m-block; 16 ch each (2 per n-block)
#pragma unroll
    for (int hrow = 0; hrow < 2; hrow++) {
      int mloc = w * 16 + g + hrow * 8;
      int r = mloc & 7, c = mloc >> 3;
      int py = tileY + r, px = tileX + c;
      size_t pix = (size_t)b * HW + (size_t)py * WW + px;
      float v[16];
#pragma unroll
      for (int nb = 0; nb < 8; nb++) {
        v[2 * nb] = dacc[nb][hrow * 2];
        v[2 * nb + 1] = dacc[nb][hrow * 2 + 1];
      }
      if (use_extra) {
#pragma unroll
        for (int nb = 0; nb < 8; nb++) {
          float2 e = *(const float2*)(g_extra + pix * 64 + nb * 8 + t4 * 2);
          v[2 * nb] += e.x; v[2 * nb + 1] += e.y;
        }
      }
#pragma unroll
      for (int i = 0; i < 16; i++) {
        int ch = (i >> 1) * 8 + t4 * 2 + (i & 1);
        float val = v[i] * sc_s[ch] + bi_s[ch];
        v[i] = val > 0.f ? val : 0.f;
      }
      if (do_proj) {
        float p0 = 0.f, p1 = 0.f, p2 = 0.f;
#pragma unroll
        for (int i = 0; i < 16; i++) {
          int ch = (i >> 1) * 8 + t4 * 2 + (i & 1);
          p0 += v[i] * wf_s[ch];
          p1 += v[i] * wf_s[64 + ch];
          p2 += v[i] * wf_s[128 + ch];
        }
#pragma unroll
        for (int m2 = 1; m2 <= 2; m2 <<= 1) {
          p0 += __shfl_xor_sync(0xffffffffu, p0, m2);
          p1 += __shfl_xor_sync(0xffffffffu, p1, m2);
          p2 += __shfl_xor_sync(0xffffffffu, p2, m2);
        }
        if (t4 == 0) {
          size_t ob = ((size_t)b * 3) * HW + (size_t)py * WW + px;
          out[ob] = p0 + bf[0];
          out[ob + HW] = p1 + bf[1];
          out[ob + 2 * HW] = p2 + bf[2];
        }
      } else {
#pragma unroll
        for (int nb = 0; nb < 8; nb++) {
          int ch = nb * 8 + t4 * 2;
          float v0 = v[2 * nb], v1 = v[2 * nb + 1];
          __nv_bfloat16 h0 = __float2bfloat16(v0), h1 = __float2bfloat16(v1);
          __nv_bfloat16 l0 = __float2bfloat16(v0 - __bfloat162float(h0));
          __nv_bfloat16 l1 = __float2bfloat16(v1 - __bfloat162float(h1));
          *(__nv_bfloat162*)(outH + pix * 64 + ch) = __nv_bfloat162(h0, h1);
          *(__nv_bfloat162*)(outL + pix * 64 + ch) = __nv_bfloat162(l0, l1);
        }
      }
    }
  }
}

// ---------------- sparse-frequency DFT chain (ch0 of act in aH1/aL1) -------
__global__ void dft_rows_kernel() {
  int n = blockIdx.x, b = blockIdx.y;
  int m = threadIdx.x;
  __shared__ float row[256], twc[256], tws[256], red[16];
  float s, c;
  sincosf((float)m * (TWO_PI / 256.f), &s, &c);
  twc[m] = c; tws[m] = s;
  size_t off = ((size_t)b * HW + (size_t)n * WW + m) * 64;
  row[m] = __bfloat162float(g_aH1[off]) + __bfloat162float(g_aL1[off]);
  __syncthreads();
  float x = row[m];
  int lane = m & 31, wid = m >> 5;
  for (int f = 0; f < 21; f++) {
    int idx = ((118 + f) * m) & 255;
    float pr = x * twc[idx];
    float pi = -x * tws[idx];
#pragma unroll
    for (int o2 = 16; o2 > 0; o2 >>= 1) {
      pr += __shfl_down_sync(0xffffffffu, pr, o2);
      pi += __shfl_down_sync(0xffffffffu, pi, o2);
    }
    if (lane == 0) { red[wid] = pr; red[8 + wid] = pi; }
    __syncthreads();
    if (m == 0) {
      float sr = 0, si = 0;
      for (int w = 0; w < 8; w++) { sr += red[w]; si += red[8 + w]; }
      g_H[((size_t)(b * 21 + f) * 256 + n) * 2] = sr;
      g_H[((size_t)(b * 21 + f) * 256 + n) * 2 + 1] = si;
    }
    __syncthreads();
  }
}

__global__ void dft_points_kernel(const float* __restrict__ message) {
  int b = blockIdx.x;
  int p = threadIdx.x;
  __shared__ float twc[256], tws[256];
  float s, c;
  sincosf((float)p * (TWO_PI / 256.f), &s, &c);
  twc[p] = c; tws[p] = s;
  __syncthreads();
  int yp = g_wy[p], xp = g_wx[p];
  int f = xp - 118;
  const float* Hp = g_H + (size_t)(b * 21 + f) * 512;
  float Fr = 0, Fi = 0;
  for (int n = 0; n < 256; n++) {
    int idx = (yp * n) & 255;
    float cc = twc[idx], ss = tws[idx];
    float hr = Hp[n * 2], hi = Hp[n * 2 + 1];
    Fr += hr * cc + hi * ss;
    Fi += hi * cc - hr * ss;
  }
  float mv = message[b * LL + p];
  g_d[(b * NP + p) * 2] = mv - Fr;
  g_d[(b * NP + p) * 2 + 1] = mv - Fi;
}

__global__ void dft_R_kernel() {
  int yf = blockIdx.x, b = blockIdx.y;
  int m = threadIdx.x;
  __shared__ float twc[256], tws[256], dsr[256], dsi[256];
  float s, c;
  sincosf((float)m * (TWO_PI / 256.f), &s, &c);
  twc[m] = c; tws[m] = s;
  dsr[m] = g_d[(b * NP + m) * 2];
  dsi[m] = g_d[(b * NP + m) * 2 + 1];
  __syncthreads();
  int yv = 118 + yf;
  float ar = 0, ai = 0;
  for (int p = 0; p < NP; p++) {
    if (g_wy[p] == yv) {
      int idx = (g_wx[p] * m) & 255;
      float cc = twc[idx], ss = tws[idx];
      float dr = dsr[p], di = dsi[p];
      ar += dr * cc - di * ss;
      ai += dr * ss + di * cc;
    }
  }
  g_R[((size_t)(b * 16 + yf) * 256 + m) * 2] = ar;
  g_R[((size_t)(b * 16 + yf) * 256 + m) * 2 + 1] = ai;
}

__global__ void dft_corr_kernel() {
  int n = blockIdx.x, b = blockIdx.y;
  int m = threadIdx.x;
  __shared__ float twc[256], tws[256];
  float s, c;
  sincosf((float)m * (TWO_PI / 256.f), &s, &c);
  twc[m] = c; tws[m] = s;
  __syncthreads();
  float acc = 0.f;
#pragma unroll
  for (int yf = 0; yf < 16; yf++) {
    int idx = ((118 + yf) * n) & 255;
    float cc = twc[idx], ss = tws[idx];
    float Rr = g_R[((size_t)(b * 16 + yf) * 256 + m) * 2];
    float Ri = g_R[((size_t)(b * 16 + yf) * 256 + m) * 2 + 1];
    acc += cc * Rr - ss * Ri;
  }
  size_t off = ((size_t)b * HW + (size_t)n * WW + m) * 64;
  float v = __bfloat162float(g_aH1[off]) + __bfloat162float(g_aL1[off]) + acc * (1.0f / 65536.0f);
  __nv_bfloat16 h = __float2bfloat16(v);
  g_aH1[off] = h;
  g_aL1[off] = __float2bfloat16(v - __bfloat162float(h));
}

extern "C" void kernel_launch(void* const* d_in, const int* in_sizes, int n_in,
                              void* d_out, int out_size) {
  const float* image   = (const float*)d_in[0];
  const float* message = (const float*)d_in[1];
  const float* w0  = (const float*)d_in[2];
  const float* b0  = (const float*)d_in[3];
  const float* g0  = (const float*)d_in[4];
  const float* be0 = (const float*)d_in[5];
  const float* m0  = (const float*)d_in[6];
  const float* v0  = (const float*)d_in[7];
  const float* wk  = (const float*)d_in[8];
  const float* bk  = (const float*)d_in[9];
  const float* gk  = (const float*)d_in[10];
  const float* bek = (const float*)d_in[11];
  const float* mk  = (const float*)d_in[12];
  const float* vk  = (const float*)d_in[13];
  const float* wa  = (const float*)d_in[14];
  const float* ba  = (const float*)d_in[15];
  const float* ga  = (const float*)d_in[16];
  const float* bea = (const float*)d_in[17];
  const float* ma  = (const float*)d_in[18];
  const float* va  = (const float*)d_in[19];
  const float* wf  = (const float*)d_in[20];
  const float* bf  = (const float*)d_in[21];
  float* out = (float*)d_out;

  cudaFuncSetAttribute(conv_mma_kernel, cudaFuncAttributeMaxDynamicSharedMemorySize, SMEM_MMA_TOTAL);

  prep_kernel<<<1, 256>>>(b0, g0, be0, m0, v0, bk, gk, bek, mk, vk, ba, ga, bea, ma, va);
  prep_w_kernel<<<576, 256>>>(wk, wa);
  msgT_kernel<<<dim3(64, NB), 256>>>(message, wa);

  dim3 sg(4, 64, NB);
  // conv0: image -> act0 (bf16 hi/lo, BN+ReLU)
  conv3_scalar_kernel<<<sg, 256>>>(image, w0, 3, 0, 0, 0, 0);
  // layer-4 side field: image channels of wa (ic 320..322) + msg taps -> raw fp32
  conv3_scalar_kernel<<<sg, 256>>>(image, wa, 323, 320, 4, 1, 1);

  dim3 mg(WW / 16, 8, NB);
  conv_mma_kernel<<<mg, 256, SMEM_MMA_TOTAL>>>(0, 0, 1, 0, 0, nullptr, nullptr, nullptr);
  conv_mma_kernel<<<mg, 256, SMEM_MMA_TOTAL>>>(1, 1, 2, 0, 0, nullptr, nullptr, nullptr);
  conv_mma_kernel<<<mg, 256, SMEM_MMA_TOTAL>>>(0, 2, 3, 0, 0, nullptr, nullptr, nullptr);

  dft_rows_kernel<<<dim3(256, NB), 256>>>();
  dft_points_kernel<<<NB, 256>>>(message);
  dft_R_kernel<<<dim3(16, NB), 256>>>();
  dft_corr_kernel<<<dim3(256, NB), 256>>>();

  // layer 4: act1 (MMA) + side field, fused BN/ReLU + 1x1 projection -> out
  conv_mma_kernel<<<mg, 256, SMEM_MMA_TOTAL>>>(1, 3, 4, 1, 1, wf, bf, out);
}

// round 7
// speedup vs baseline: 3.3085x; 1.0006x over previous
#include <cuda_runtime.h>
#include <cuda_bf16.h>
#include <math.h>
#include <stdint.h>

#define HH 256
#define WW 256
#define HW 65536
#define NB 16
#define CC 64
#define LL 256
#define NP 256

__device__ __nv_bfloat16 g_aH0[NB * HW * 64];
__device__ __nv_bfloat16 g_aL0[NB * HW * 64];
__device__ __nv_bfloat16 g_aH1[NB * HW * 64];
__device__ __nv_bfloat16 g_aL1[NB * HW * 64];
__device__ float g_extra[NB * HW * 64];
__device__ __nv_bfloat16 g_wH[4 * 9 * 64 * 64];
__device__ __nv_bfloat16 g_wL[4 * 9 * 64 * 64];
__device__ float g_H[NB * 21 * 256 * 2];
__device__ float g_d[NB * NP * 2];
__device__ float g_R[NB * 16 * 256 * 2];
__device__ float g_T[NB * CC * 9];
__device__ float g_scale[5 * CC];
__device__ float g_bias[5 * CC];
__device__ int   g_wy[NP];
__device__ int   g_wx[NP];

#define TWO_PI 6.283185307179586f

#define FMA_F32X2(d, a, b) \
  asm("fma.rn.f32x2 %0, %1, %2, %0;" : "+l"(d) : "l"(a), "l"(b))
#define ADD_F32X2_(d, a, b) \
  asm("add.rn.f32x2 %0, %1, %2;" : "=l"(d) : "l"(a), "l"(b))
#define PACK_DUP(out, v) \
  asm("mov.b64 %0, {%1, %1};" : "=l"(out) : "r"(__float_as_uint(v)))
#define UNPACK_2(lo, hi, in) \
  asm("mov.b64 {%0, %1}, %2;" : "=r"(lo), "=r"(hi) : "l"(in))

__device__ __forceinline__ uint32_t smem_u32(const void* p) {
  uint32_t a;
  asm("{ .reg .u64 t; cvta.to.shared.u64 t, %1; cvt.u32.u64 %0, t; }" : "=r"(a) : "l"(p));
  return a;
}
#define LDM4(r, addr) \
  asm volatile("ldmatrix.sync.aligned.m8n8.x4.shared.b16 {%0,%1,%2,%3}, [%4];" \
    : "=r"((r)[0]), "=r"((r)[1]), "=r"((r)[2]), "=r"((r)[3]) : "r"(addr))
#define MMA16816(d, a, b0, b1) \
  asm volatile("mma.sync.aligned.m16n8k16.row.col.f32.bf16.bf16.f32 " \
    "{%0,%1,%2,%3}, {%4,%5,%6,%7}, {%8,%9}, {%0,%1,%2,%3};" \
    : "+f"((d)[0]), "+f"((d)[1]), "+f"((d)[2]), "+f"((d)[3]) \
    : "r"((a)[0]), "r"((a)[1]), "r"((a)[2]), "r"((a)[3]), "r"(b0), "r"(b1))

#define ACT_H 1536
#define ACT_L 27456
#define WGT_H 53376
#define WGT_L 136320
#define SMEM_MMA_TOTAL 219264
#define PST 144

__global__ void prep_kernel(const float* b0, const float* g0, const float* be0,
                            const float* m0, const float* v0,
                            const float* bk, const float* gk, const float* bek,
                            const float* mk, const float* vk,
                            const float* ba, const float* ga, const float* bea,
                            const float* ma, const float* va) {
  int c = threadIdx.x;
  const float EPS = 1e-5f;
  if (c < CC) {
    float s = g0[c] * rsqrtf(v0[c] + EPS);
    g_scale[c] = s;
    g_bias[c] = be0[c] + (b0[c] - m0[c]) * s;
    for (int t = 0; t < 3; t++) {
      float st = gk[t * CC + c] * rsqrtf(vk[t * CC + c] + EPS);
      g_scale[(1 + t) * CC + c] = st;
      g_bias[(1 + t) * CC + c] = bek[t * CC + c] + (bk[t * CC + c] - mk[t * CC + c]) * st;
    }
    float sa = ga[c] * rsqrtf(va[c] + EPS);
    g_scale[4 * CC + c] = sa;
    g_bias[4 * CC + c] = bea[c] + (ba[c] - ma[c]) * sa;
  }
  if (c == 0) {
    int cnt = 0;
    for (int ch = 0; ch < CC && cnt < NP; ch++)
      for (int i = -10; i <= 10 && cnt < NP; i++)
        for (int j = -10; j <= 10; j++) {
          if (cnt >= NP) break;
          int y = 128 + i, x = 128 + j;
          if (y >= 0 && y < HH && x >= 0 && x < WW && (i * i + j * j <= 100)) {
            g_wy[cnt] = y; g_wx[cnt] = x; cnt++;
          }
        }
  }
}

__global__ void prep_w_kernel(const float* __restrict__ wk, const float* __restrict__ wa) {
  int i = blockIdx.x * 256 + threadIdx.x;
  int l = i / 36864;
  int rem = i - l * 36864;
  int t = rem / 4096;
  int r2 = rem & 4095;
  int oc = r2 >> 6, ic = r2 & 63;
  float w = (l < 3) ? wk[(((size_t)l * 64 + oc) * 64 + ic) * 9 + t]
                    : wa[((size_t)oc * 323 + 256 + ic) * 9 + t];
  __nv_bfloat16 h = __float2bfloat16(w);
  g_wH[i] = h;
  g_wL[i] = __float2bfloat16(w - __bfloat162float(h));
}

__global__ void msgT_kernel(const float* __restrict__ message,
                            const float* __restrict__ wa) {
  int o = blockIdx.x, b = blockIdx.y;
  int c = threadIdx.x;
  __shared__ float red[8];
  float mv = message[b * LL + c];
  const float* wp = wa + ((size_t)o * 323 + c) * 9;
  for (int t = 0; t < 9; t++) {
    float v = mv * wp[t];
#pragma unroll
    for (int off = 16; off > 0; off >>= 1) v += __shfl_down_sync(0xffffffffu, v, off);
    if ((c & 31) == 0) red[c >> 5] = v;
    __syncthreads();
    if (c == 0) {
      float s = 0;
      for (int w2 = 0; w2 < 8; w2++) s += red[w2];
      g_T[(b * CC + o) * 9 + t] = s;
    }
    __syncthreads();
  }
}

// fused scalar FFMA2 conv: blockIdx.z in [0,32): b=z&15, mode=z>>4.
// mode 0: conv0 (w0), BN+ReLU -> g_aH0/g_aL0.  mode 1: wa image-ch + msg taps -> g_extra raw.
__launch_bounds__(256, 2)
__global__ void conv3_scalar_kernel(const float* __restrict__ ext_in,
                                    const float* __restrict__ w0,
                                    const float* __restrict__ wa) {
  __shared__ __align__(16) float w_s[3 * 144];
  __shared__ __align__(16) float tile[2][34 * 34 + 2];
  __shared__ __align__(16) float T_s[16 * 9];

  int tid = threadIdx.x;
  int ocg = blockIdx.x, tileId = blockIdx.y;
  int zz = blockIdx.z;
  int b = zz & 15, mode = zz >> 4;
  int y0 = (tileId >> 3) << 5, x0 = (tileId & 7) << 5;

  const float* Wt = mode ? wa : w0;
  int CW = mode ? 323 : 3;
  int ic0 = mode ? 320 : 0;
  int layer = mode ? 4 : 0;
  int use_msg = mode;

  int Wstride = CW * 9;
  for (int idx = tid; idx < 3 * 144; idx += 256) {
    int c = idx / 144;
    int rem = idx - c * 144;
    int t = rem >> 4;
    int oc = rem & 15;
    w_s[idx] = Wt[(size_t)(ocg * 16 + oc) * Wstride + (ic0 + c) * 9 + t];
  }
  if (use_msg && tid < 144)
    T_s[(tid % 9) * 16 + (tid / 9)] = g_T[(b * CC + ocg * 16 + (tid / 9)) * 9 + (tid % 9)];

  int tx = tid & 31, ty = tid >> 5;
  unsigned long long acc2[4][8];
#pragma unroll
  for (int k = 0; k < 4; k++)
#pragma unroll
    for (int o = 0; o < 8; o++) acc2[k][o] = 0ull;

  {
    const float* src0 = ext_in + ((size_t)(b * 3)) * HW;
    for (int idx = tid; idx < 34 * 34; idx += 256) {
      int r = idx / 34, cl = idx - r * 34;
      int gy = y0 + r - 1, gx = x0 + cl - 1;
      float v = 0.f;
      if (gy >= 0 && gy < HH && gx >= 0 && gx < WW) v = src0[gy * WW + gx];
      tile[0][idx] = v;
    }
  }
  __syncthreads();

  if (use_msg) {
#pragma unroll
    for (int kh = 0; kh < 3; kh++) {
#pragma unroll
      for (int kw = 0; kw < 3; kw++) {
        int t = kh * 3 + kw;
        const unsigned long long* tp = (const unsigned long long*)(T_s + t * 16);
        unsigned long long tpr[8];
#pragma unroll
        for (int o = 0; o < 8; o++) tpr[o] = tp[o];
#pragma unroll
        for (int k = 0; k < 4; k++) {
          int iy = y0 + ty + 8 * k + kh - 1;
          int ix = x0 + tx + kw - 1;
          if (iy >= 0 && iy < HH && ix >= 0 && ix < WW) {
#pragma unroll
            for (int o = 0; o < 8; o++) ADD_F32X2_(acc2[k][o], acc2[k][o], tpr[o]);
          }
        }
      }
    }
  }

  for (int c = 0; c < 3; c++) {
    int cur = c & 1, nxt = cur ^ 1;
    float pre[5];
    bool havePre = (c + 1 < 3);
    if (havePre) {
      const float* srcn = ext_in + ((size_t)(b * 3 + c + 1)) * HW;
#pragma unroll
      for (int i = 0; i < 5; i++) {
        int idx = tid + 256 * i;
        float v = 0.f;
        if (idx < 34 * 34) {
          int r = idx / 34, cl = idx - r * 34;
          int gy = y0 + r - 1, gx = x0 + cl - 1;
          if (gy >= 0 && gy < HH && gx >= 0 && gx < WW) v = srcn[gy * WW + gx];
        }
        pre[i] = v;
      }
    }
    const float* wc = w_s + c * 144;
    const float* trow = tile[cur] + ty * 34 + tx;
#pragma unroll
    for (int kh = 0; kh < 3; kh++) {
#pragma unroll
      for (int kw = 0; kw < 3; kw++) {
        int t = kh * 3 + kw;
        const unsigned long long* wp2 = (const unsigned long long*)(wc + t * 16);
        unsigned long long wp[8];
#pragma unroll
        for (int o = 0; o < 8; o += 2) {
          ulonglong2 q = *(const ulonglong2*)(wp2 + o);
          wp[o] = q.x; wp[o + 1] = q.y;
        }
#pragma unroll
        for (int k = 0; k < 4; k++) {
          float v = trow[(8 * k + kh) * 34 + kw];
          unsigned long long vv;
          PACK_DUP(vv, v);
#pragma unroll
          for (int o = 0; o < 8; o++) FMA_F32X2(acc2[k][o], vv, wp[o]);
        }
      }
    }
    if (havePre) {
#pragma unroll
      for (int i = 0; i < 5; i++) {
        int idx = tid + 256 * i;
        if (idx < 34 * 34) tile[nxt][idx] = pre[i];
      }
    }
    __syncthreads();
  }

  const float* scp = g_scale + layer * CC + ocg * 16;
  const float* bip = g_bias + layer * CC + ocg * 16;
#pragma unroll
  for (int k = 0; k < 4; k++) {
    int y = y0 + ty + 8 * k;
    size_t pixb = ((size_t)b * HW + (size_t)y * WW + x0 + tx) * 64 + ocg * 16;
    float r[16];
#pragma unroll
    for (int o = 0; o < 8; o++) {
      unsigned lo, hi;
      UNPACK_2(lo, hi, acc2[k][o]);
      r[2 * o] = __uint_as_float(lo);
      r[2 * o + 1] = __uint_as_float(hi);
    }
    if (mode == 0) {
      __nv_bfloat16 hb[16], lb[16];
#pragma unroll
      for (int o = 0; o < 16; o++) {
        float v = r[o] * scp[o] + bip[o];
        v = v > 0.f ? v : 0.f;
        __nv_bfloat16 h = __float2bfloat16(v);
        hb[o] = h;
        lb[o] = __float2bfloat16(v - __bfloat162float(h));
      }
      uint4* dh = (uint4*)(g_aH0 + pixb);
      uint4* dl = (uint4*)(g_aL0 + pixb);
      dh[0] = ((uint4*)hb)[0]; dh[1] = ((uint4*)hb)[1];
      dl[0] = ((uint4*)lb)[0]; dl[1] = ((uint4*)lb)[1];
    } else {
      uint4* df = (uint4*)(g_extra + pixb);
#pragma unroll
      for (int q = 0; q < 4; q++) df[q] = ((uint4*)r)[q];
    }
  }
}

// HMMA bf16-split implicit-GEMM 3x3 conv. Accumulator-independent MMA schedule.
__launch_bounds__(256, 1)
__global__ void conv_mma_kernel(int srcSel, int wslot, int layer,
                                int use_extra, int do_proj,
                                const float* __restrict__ wf,
                                const float* __restrict__ bf,
                                float* __restrict__ out) {
  extern __shared__ __align__(16) char smem[];
  float* sc_s = (float*)(smem + 0);
  float* bi_s = (float*)(smem + 256);
  float* wf_s = (float*)(smem + 512);

  int tid = threadIdx.x, w = tid >> 5, lane = tid & 31;
  int tileX = blockIdx.x * 16, b = blockIdx.z;

  const __nv_bfloat16* inH = srcSel ? g_aH1 : g_aH0;
  const __nv_bfloat16* inL = srcSel ? g_aL1 : g_aL0;
  __nv_bfloat16* outH = srcSel ? g_aH0 : g_aH1;
  __nv_bfloat16* outL = srcSel ? g_aL0 : g_aL1;
  const __nv_bfloat16* wHs = g_wH + wslot * 36864;
  const __nv_bfloat16* wLs = g_wL + wslot * 36864;

  for (int idx = tid; idx < 9216; idx += 256) {
    int half = idx >= 4608;
    int i = half ? idx - 4608 : idx;
    int t = i >> 9;
    int oc = (i >> 3) & 63;
    int ich = i & 7;
    uint4 v = *(const uint4*)((half ? wLs : wHs) + ((size_t)(t * 64 + oc) * 64 + ich * 8));
    *(uint4*)(smem + (half ? WGT_L : WGT_H) + t * 9216 + oc * PST + ich * 16) = v;
  }
  if (tid < 64) { sc_s[tid] = g_scale[layer * CC + tid]; bi_s[tid] = g_bias[layer * CC + tid]; }
  if (do_proj && tid >= 64 && tid < 256) wf_s[tid - 64] = wf[tid - 64];

  uint32_t sb = smem_u32(smem);
  int mL = lane & 15;
  int rL = mL & 7, cL = w * 2 + (mL >> 3);
  uint32_t baseA = (uint32_t)((rL * 18 + cL) * PST + (lane >> 4) * 16);
  uint32_t baseB = (uint32_t)((lane & 7) * PST + ((lane >> 3) & 1) * 16 + (lane >> 4) * (8 * PST));
  int g = lane >> 2, t4 = lane & 3;

  for (int yt = 0; yt < 4; yt++) {
    int tileY = (blockIdx.y * 4 + yt) * 8;
    __syncthreads();

    for (int idx = tid; idx < 2880; idx += 256) {
      int half = idx >= 1440;
      int i = half ? idx - 1440 : idx;
      int r10 = i / 144;
      int rem = i - r10 * 144;
      int c18 = rem >> 3, och = rem & 7;
      int gy = tileY - 1 + r10, gx = tileX - 1 + c18;
      uint4 v = make_uint4(0, 0, 0, 0);
      if (gy >= 0 && gy < HH && gx >= 0 && gx < WW)
        v = *(const uint4*)((half ? inL : inH) + (((size_t)b * HW + (size_t)gy * WW + gx) * 64 + och * 8));
      *(uint4*)(smem + (half ? ACT_L : ACT_H) + (r10 * 18 + c18) * PST + och * 16) = v;
    }
    __syncthreads();

    float dacc[8][4];
#pragma unroll
    for (int nb = 0; nb < 8; nb++)
#pragma unroll
      for (int q = 0; q < 4; q++) dacc[nb][q] = 0.f;

    for (int t = 0; t < 9; t++) {
      int toff = ((t / 3) * 18 + (t % 3)) * PST;
      uint32_t aH_t = sb + ACT_H + baseA + toff;
      uint32_t aL_t = sb + ACT_L + baseA + toff;
      uint32_t wH_t = sb + WGT_H + t * 9216 + baseB;
      uint32_t wL_t = sb + WGT_L + t * 9216 + baseB;
#pragma unroll
      for (int kb = 0; kb < 4; kb++) {
        uint32_t ah[4], al[4], bh[4][4], bl[4][4];
        LDM4(ah, aH_t + kb * 32);
        LDM4(al, aL_t + kb * 32);
#pragma unroll
        for (int j = 0; j < 4; j++) {
          LDM4(bh[j], wH_t + j * 2304 + kb * 32);
          LDM4(bl[j], wL_t + j * 2304 + kb * 32);
        }
        // pass 1: ah*bh — 8 MMAs, all distinct accumulators
#pragma unroll
        for (int j = 0; j < 4; j++) {
          MMA16816(dacc[2 * j], ah, bh[j][0], bh[j][1]);
          MMA16816(dacc[2 * j + 1], ah, bh[j][2], bh[j][3]);
        }
        // pass 2: al*bh
#pragma unroll
        for (int j = 0; j < 4; j++) {
          MMA16816(dacc[2 * j], al, bh[j][0], bh[j][1]);
          MMA16816(dacc[2 * j + 1], al, bh[j][2], bh[j][3]);
        }
        // pass 3: ah*bl
#pragma unroll
        for (int j = 0; j < 4; j++) {
          MMA16816(dacc[2 * j], ah, bl[j][0], bl[j][1]);
          MMA16816(dacc[2 * j + 1], ah, bl[j][2], bl[j][3]);
        }
      }
    }

#pragma unroll
    for (int hrow = 0; hrow < 2; hrow++) {
      int mloc = w * 16 + g + hrow * 8;
      int r = mloc & 7, c = mloc >> 3;
      int py = tileY + r, px = tileX + c;
      size_t pix = (size_t)b * HW + (size_t)py * WW + px;
      float v[16];
#pragma unroll
      for (int nb = 0; nb < 8; nb++) {
        v[2 * nb] = dacc[nb][hrow * 2];
        v[2 * nb + 1] = dacc[nb][hrow * 2 + 1];
      }
      if (use_extra) {
#pragma unroll
        for (int nb = 0; nb < 8; nb++) {
          float2 e = *(const float2*)(g_extra + pix * 64 + nb * 8 + t4 * 2);
          v[2 * nb] += e.x; v[2 * nb + 1] += e.y;
        }
      }
#pragma unroll
      for (int i = 0; i < 16; i++) {
        int ch = (i >> 1) * 8 + t4 * 2 + (i & 1);
        float val = v[i] * sc_s[ch] + bi_s[ch];
        v[i] = val > 0.f ? val : 0.f;
      }
      if (do_proj) {
        float p0 = 0.f, p1 = 0.f, p2 = 0.f;
#pragma unroll
        for (int i = 0; i < 16; i++) {
          int ch = (i >> 1) * 8 + t4 * 2 + (i & 1);
          p0 += v[i] * wf_s[ch];
          p1 += v[i] * wf_s[64 + ch];
          p2 += v[i] * wf_s[128 + ch];
        }
#pragma unroll
        for (int m2 = 1; m2 <= 2; m2 <<= 1) {
          p0 += __shfl_xor_sync(0xffffffffu, p0, m2);
          p1 += __shfl_xor_sync(0xffffffffu, p1, m2);
          p2 += __shfl_xor_sync(0xffffffffu, p2, m2);
        }
        if (t4 == 0) {
          size_t ob = ((size_t)b * 3) * HW + (size_t)py * WW + px;
          out[ob] = p0 + bf[0];
          out[ob + HW] = p1 + bf[1];
          out[ob + 2 * HW] = p2 + bf[2];
        }
      } else {
#pragma unroll
        for (int nb = 0; nb < 8; nb++) {
          int ch = nb * 8 + t4 * 2;
          float v0 = v[2 * nb], v1 = v[2 * nb + 1];
          __nv_bfloat16 h0 = __float2bfloat16(v0), h1 = __float2bfloat16(v1);
          __nv_bfloat16 l0 = __float2bfloat16(v0 - __bfloat162float(h0));
          __nv_bfloat16 l1 = __float2bfloat16(v1 - __bfloat162float(h1));
          *(__nv_bfloat162*)(outH + pix * 64 + ch) = __nv_bfloat162(h0, h1);
          *(__nv_bfloat162*)(outL + pix * 64 + ch) = __nv_bfloat162(l0, l1);
        }
      }
    }
  }
}

__global__ void dft_rows_kernel() {
  int n = blockIdx.x, b = blockIdx.y;
  int m = threadIdx.x;
  __shared__ float row[256], twc[256], tws[256], red[16];
  float s, c;
  sincosf((float)m * (TWO_PI / 256.f), &s, &c);
  twc[m] = c; tws[m] = s;
  size_t off = ((size_t)b * HW + (size_t)n * WW + m) * 64;
  row[m] = __bfloat162float(g_aH1[off]) + __bfloat162float(g_aL1[off]);
  __syncthreads();
  float x = row[m];
  int lane = m & 31, wid = m >> 5;
  for (int f = 0; f < 21; f++) {
    int idx = ((118 + f) * m) & 255;
    float pr = x * twc[idx];
    float pi = -x * tws[idx];
#pragma unroll
    for (int o2 = 16; o2 > 0; o2 >>= 1) {
      pr += __shfl_down_sync(0xffffffffu, pr, o2);
      pi += __shfl_down_sync(0xffffffffu, pi, o2);
    }
    if (lane == 0) { red[wid] = pr; red[8 + wid] = pi; }
    __syncthreads();
    if (m == 0) {
      float sr = 0, si = 0;
      for (int w = 0; w < 8; w++) { sr += red[w]; si += red[8 + w]; }
      g_H[((size_t)(b * 21 + f) * 256 + n) * 2] = sr;
      g_H[((size_t)(b * 21 + f) * 256 + n) * 2 + 1] = si;
    }
    __syncthreads();
  }
}

__global__ void dft_points_kernel(const float* __restrict__ message) {
  int b = blockIdx.x;
  int p = threadIdx.x;
  __shared__ float twc[256], tws[256];
  float s, c;
  sincosf((float)p * (TWO_PI / 256.f), &s, &c);
  twc[p] = c; tws[p] = s;
  __syncthreads();
  int yp = g_wy[p], xp = g_wx[p];
  int f = xp - 118;
  const float* Hp = g_H + (size_t)(b * 21 + f) * 512;
  float Fr = 0, Fi = 0;
  for (int n = 0; n < 256; n++) {
    int idx = (yp * n) & 255;
    float cc = twc[idx], ss = tws[idx];
    float hr = Hp[n * 2], hi = Hp[n * 2 + 1];
    Fr += hr * cc + hi * ss;
    Fi += hi * cc - hr * ss;
  }
  float mv = message[b * LL + p];
  g_d[(b * NP + p) * 2] = mv - Fr;
  g_d[(b * NP + p) * 2 + 1] = mv - Fi;
}

__global__ void dft_R_kernel() {
  int yf = blockIdx.x, b = blockIdx.y;
  int m = threadIdx.x;
  __shared__ float twc[256], tws[256], dsr[256], dsi[256];
  float s, c;
  sincosf((float)m * (TWO_PI / 256.f), &s, &c);
  twc[m] = c; tws[m] = s;
  dsr[m] = g_d[(b * NP + m) * 2];
  dsi[m] = g_d[(b * NP + m) * 2 + 1];
  __syncthreads();
  int yv = 118 + yf;
  float ar = 0, ai = 0;
  for (int p = 0; p < NP; p++) {
    if (g_wy[p] == yv) {
      int idx = (g_wx[p] * m) & 255;
      float cc = twc[idx], ss = tws[idx];
      float dr = dsr[p], di = dsi[p];
      ar += dr * cc - di * ss;
      ai += dr * ss + di * cc;
    }
  }
  g_R[((size_t)(b * 16 + yf) * 256 + m) * 2] = ar;
  g_R[((size_t)(b * 16 + yf) * 256 + m) * 2 + 1] = ai;
}

__global__ void dft_corr_kernel() {
  int n = blockIdx.x, b = blockIdx.y;
  int m = threadIdx.x;
  __shared__ float twc[256], tws[256];
  float s, c;
  sincosf((float)m * (TWO_PI / 256.f), &s, &c);
  twc[m] = c; tws[m] = s;
  __syncthreads();
  float acc = 0.f;
#pragma unroll
  for (int yf = 0; yf < 16; yf++) {
    int idx = ((118 + yf) * n) & 255;
    float cc = twc[idx], ss = tws[idx];
    float Rr = g_R[((size_t)(b * 16 + yf) * 256 + m) * 2];
    float Ri = g_R[((size_t)(b * 16 + yf) * 256 + m) * 2 + 1];
    acc += cc * Rr - ss * Ri;
  }
  size_t off = ((size_t)b * HW + (size_t)n * WW + m) * 64;
  float v = __bfloat162float(g_aH1[off]) + __bfloat162float(g_aL1[off]) + acc * (1.0f / 65536.0f);
  __nv_bfloat16 h = __float2bfloat16(v);
  g_aH1[off] = h;
  g_aL1[off] = __float2bfloat16(v - __bfloat162float(h));
}

extern "C" void kernel_launch(void* const* d_in, const int* in_sizes, int n_in,
                              void* d_out, int out_size) {
  const float* image   = (const float*)d_in[0];
  const float* message = (const float*)d_in[1];
  const float* w0  = (const float*)d_in[2];
  const float* b0  = (const float*)d_in[3];
  const float* g0  = (const float*)d_in[4];
  const float* be0 = (const float*)d_in[5];
  const float* m0  = (const float*)d_in[6];
  const float* v0  = (const float*)d_in[7];
  const float* wk  = (const float*)d_in[8];
  const float* bk  = (const float*)d_in[9];
  const float* gk  = (const float*)d_in[10];
  const float* bek = (const float*)d_in[11];
  const float* mk  = (const float*)d_in[12];
  const float* vk  = (const float*)d_in[13];
  const float* wa  = (const float*)d_in[14];
  const float* ba  = (const float*)d_in[15];
  const float* ga  = (const float*)d_in[16];
  const float* bea = (const float*)d_in[17];
  const float* ma  = (const float*)d_in[18];
  const float* va  = (const float*)d_in[19];
  const float* wf  = (const float*)d_in[20];
  const float* bf  = (const float*)d_in[21];
  float* out = (float*)d_out;

  cudaFuncSetAttribute(conv_mma_kernel, cudaFuncAttributeMaxDynamicSharedMemorySize, SMEM_MMA_TOTAL);

  prep_kernel<<<1, 256>>>(b0, g0, be0, m0, v0, bk, gk, bek, mk, vk, ba, ga, bea, ma, va);
  prep_w_kernel<<<576, 256>>>(wk, wa);
  msgT_kernel<<<dim3(64, NB), 256>>>(message, wa);

  // fused scalar convs: conv0 (mode 0, z<16) + layer-4 side field (mode 1, z>=16)
  conv3_scalar_kernel<<<dim3(4, 64, 2 * NB), 256>>>(image, w0, wa);

  dim3 mg(WW / 16, 8, NB);
  conv_mma_kernel<<<mg, 256, SMEM_MMA_TOTAL>>>(0, 0, 1, 0, 0, nullptr, nullptr, nullptr);
  conv_mma_kernel<<<mg, 256, SMEM_MMA_TOTAL>>>(1, 1, 2, 0, 0, nullptr, nullptr, nullptr);
  conv_mma_kernel<<<mg, 256, SMEM_MMA_TOTAL>>>(0, 2, 3, 0, 0, nullptr, nullptr, nullptr);

  dft_rows_kernel<<<dim3(256, NB), 256>>>();
  dft_points_kernel<<<NB, 256>>>(message);
  dft_R_kernel<<<dim3(16, NB), 256>>>();
  dft_corr_kernel<<<dim3(256, NB), 256>>>();

  conv_mma_kernel<<<mg, 256, SMEM_MMA_TOTAL>>>(1, 3, 4, 1, 1, wf, bf, out);
}

// round 8
// speedup vs baseline: 3.9108x; 1.1821x over previous
#include <cuda_runtime.h>
#include <cuda_fp16.h>
#include <math.h>
#include <stdint.h>

#define HH 256
#define WW 256
#define HW 65536
#define NB 16
#define CC 64
#define LL 256
#define NP 256

__device__ __half g_aH0[NB * HW * 64];
__device__ __half g_aL0[NB * HW * 64];
__device__ __half g_aH1[NB * HW * 64];
__device__ __half g_aL1[NB * HW * 64];
__device__ float g_extra[NB * HW * 64];
__device__ __half g_wH[4 * 9 * 64 * 64];   // [slot][tap][oc][ic] fp16
__device__ float g_H[NB * 21 * 256 * 2];
__device__ float g_d[NB * NP * 2];
__device__ float g_R[NB * 16 * 256 * 2];
__device__ float g_T[NB * CC * 9];
__device__ float g_scale[5 * CC];
__device__ float g_bias[5 * CC];
__device__ int   g_wy[NP];
__device__ int   g_wx[NP];

#define TWO_PI 6.283185307179586f

#define FMA_F32X2(d, a, b) \
  asm("fma.rn.f32x2 %0, %1, %2, %0;" : "+l"(d) : "l"(a), "l"(b))
#define ADD_F32X2_(d, a, b) \
  asm("add.rn.f32x2 %0, %1, %2;" : "=l"(d) : "l"(a), "l"(b))
#define PACK_DUP(out, v) \
  asm("mov.b64 %0, {%1, %1};" : "=l"(out) : "r"(__float_as_uint(v)))
#define UNPACK_2(lo, hi, in) \
  asm("mov.b64 {%0, %1}, %2;" : "=r"(lo), "=r"(hi) : "l"(in))

__device__ __forceinline__ uint32_t smem_u32(const void* p) {
  uint32_t a;
  asm("{ .reg .u64 t; cvta.to.shared.u64 t, %1; cvt.u32.u64 %0, t; }" : "=r"(a) : "l"(p));
  return a;
}
#define LDM4(r, addr) \
  asm volatile("ldmatrix.sync.aligned.m8n8.x4.shared.b16 {%0,%1,%2,%3}, [%4];" \
    : "=r"((r)[0]), "=r"((r)[1]), "=r"((r)[2]), "=r"((r)[3]) : "r"(addr))
#define MMA16816(d, a, b0, b1) \
  asm volatile("mma.sync.aligned.m16n8k16.row.col.f32.f16.f16.f32 " \
    "{%0,%1,%2,%3}, {%4,%5,%6,%7}, {%8,%9}, {%0,%1,%2,%3};" \
    : "+f"((d)[0]), "+f"((d)[1]), "+f"((d)[2]), "+f"((d)[3]) \
    : "r"((a)[0]), "r"((a)[1]), "r"((a)[2]), "r"((a)[3]), "r"(b0), "r"(b1))

#define ACT_H 1536
#define ACT_L 27456
#define WGT_H 53376
#define SMEM_MMA_TOTAL 136320
#define PST 144

__global__ void prep_kernel(const float* b0, const float* g0, const float* be0,
                            const float* m0, const float* v0,
                            const float* bk, const float* gk, const float* bek,
                            const float* mk, const float* vk,
                            const float* ba, const float* ga, const float* bea,
                            const float* ma, const float* va) {
  int c = threadIdx.x;
  const float EPS = 1e-5f;
  if (c < CC) {
    float s = g0[c] * rsqrtf(v0[c] + EPS);
    g_scale[c] = s;
    g_bias[c] = be0[c] + (b0[c] - m0[c]) * s;
    for (int t = 0; t < 3; t++) {
      float st = gk[t * CC + c] * rsqrtf(vk[t * CC + c] + EPS);
      g_scale[(1 + t) * CC + c] = st;
      g_bias[(1 + t) * CC + c] = bek[t * CC + c] + (bk[t * CC + c] - mk[t * CC + c]) * st;
    }
    float sa = ga[c] * rsqrtf(va[c] + EPS);
    g_scale[4 * CC + c] = sa;
    g_bias[4 * CC + c] = bea[c] + (ba[c] - ma[c]) * sa;
  }
  if (c == 0) {
    int cnt = 0;
    for (int ch = 0; ch < CC && cnt < NP; ch++)
      for (int i = -10; i <= 10 && cnt < NP; i++)
        for (int j = -10; j <= 10; j++) {
          if (cnt >= NP) break;
          int y = 128 + i, x = 128 + j;
          if (y >= 0 && y < HH && x >= 0 && x < WW && (i * i + j * j <= 100)) {
            g_wy[cnt] = y; g_wx[cnt] = x; cnt++;
          }
        }
  }
}

__global__ void prep_w_kernel(const float* __restrict__ wk, const float* __restrict__ wa) {
  int i = blockIdx.x * 256 + threadIdx.x;
  int l = i / 36864;
  int rem = i - l * 36864;
  int t = rem / 4096;
  int r2 = rem & 4095;
  int oc = r2 >> 6, ic = r2 & 63;
  float w = (l < 3) ? wk[(((size_t)l * 64 + oc) * 64 + ic) * 9 + t]
                    : wa[((size_t)oc * 323 + 256 + ic) * 9 + t];
  g_wH[i] = __float2half(w);
}

__global__ void msgT_kernel(const float* __restrict__ message,
                            const float* __restrict__ wa) {
  int o = blockIdx.x, b = blockIdx.y;
  int c = threadIdx.x;
  __shared__ float red[8];
  float mv = message[b * LL + c];
  const float* wp = wa + ((size_t)o * 323 + c) * 9;
  for (int t = 0; t < 9; t++) {
    float v = mv * wp[t];
#pragma unroll
    for (int off = 16; off > 0; off >>= 1) v += __shfl_down_sync(0xffffffffu, v, off);
    if ((c & 31) == 0) red[c >> 5] = v;
    __syncthreads();
    if (c == 0) {
      float s = 0;
      for (int w2 = 0; w2 < 8; w2++) s += red[w2];
      g_T[(b * CC + o) * 9 + t] = s;
    }
    __syncthreads();
  }
}

// fused scalar FFMA2 conv: blockIdx.z in [0,32): b=z&15, mode=z>>4.
__launch_bounds__(256, 2)
__global__ void conv3_scalar_kernel(const float* __restrict__ ext_in,
                                    const float* __restrict__ w0,
                                    const float* __restrict__ wa) {
  __shared__ __align__(16) float w_s[3 * 144];
  __shared__ __align__(16) float tile[2][34 * 34 + 2];
  __shared__ __align__(16) float T_s[16 * 9];

  int tid = threadIdx.x;
  int ocg = blockIdx.x, tileId = blockIdx.y;
  int zz = blockIdx.z;
  int b = zz & 15, mode = zz >> 4;
  int y0 = (tileId >> 3) << 5, x0 = (tileId & 7) << 5;

  const float* Wt = mode ? wa : w0;
  int CW = mode ? 323 : 3;
  int ic0 = mode ? 320 : 0;
  int layer = mode ? 4 : 0;
  int use_msg = mode;

  int Wstride = CW * 9;
  for (int idx = tid; idx < 3 * 144; idx += 256) {
    int c = idx / 144;
    int rem = idx - c * 144;
    int t = rem >> 4;
    int oc = rem & 15;
    w_s[idx] = Wt[(size_t)(ocg * 16 + oc) * Wstride + (ic0 + c) * 9 + t];
  }
  if (use_msg && tid < 144)
    T_s[(tid % 9) * 16 + (tid / 9)] = g_T[(b * CC + ocg * 16 + (tid / 9)) * 9 + (tid % 9)];

  int tx = tid & 31, ty = tid >> 5;
  unsigned long long acc2[4][8];
#pragma unroll
  for (int k = 0; k < 4; k++)
#pragma unroll
    for (int o = 0; o < 8; o++) acc2[k][o] = 0ull;

  {
    const float* src0 = ext_in + ((size_t)(b * 3)) * HW;
    for (int idx = tid; idx < 34 * 34; idx += 256) {
      int r = idx / 34, cl = idx - r * 34;
      int gy = y0 + r - 1, gx = x0 + cl - 1;
      float v = 0.f;
      if (gy >= 0 && gy < HH && gx >= 0 && gx < WW) v = src0[gy * WW + gx];
      tile[0][idx] = v;
    }
  }
  __syncthreads();

  if (use_msg) {
#pragma unroll
    for (int kh = 0; kh < 3; kh++) {
#pragma unroll
      for (int kw = 0; kw < 3; kw++) {
        int t = kh * 3 + kw;
        const unsigned long long* tp = (const unsigned long long*)(T_s + t * 16);
        unsigned long long tpr[8];
#pragma unroll
        for (int o = 0; o < 8; o++) tpr[o] = tp[o];
#pragma unroll
        for (int k = 0; k < 4; k++) {
          int iy = y0 + ty + 8 * k + kh - 1;
          int ix = x0 + tx + kw - 1;
          if (iy >= 0 && iy < HH && ix >= 0 && ix < WW) {
#pragma unroll
            for (int o = 0; o < 8; o++) ADD_F32X2_(acc2[k][o], acc2[k][o], tpr[o]);
          }
        }
      }
    }
  }

  for (int c = 0; c < 3; c++) {
    int cur = c & 1, nxt = cur ^ 1;
    float pre[5];
    bool havePre = (c + 1 < 3);
    if (havePre) {
      const float* srcn = ext_in + ((size_t)(b * 3 + c + 1)) * HW;
#pragma unroll
      for (int i = 0; i < 5; i++) {
        int idx = tid + 256 * i;
        float v = 0.f;
        if (idx < 34 * 34) {
          int r = idx / 34, cl = idx - r * 34;
          int gy = y0 + r - 1, gx = x0 + cl - 1;
          if (gy >= 0 && gy < HH && gx >= 0 && gx < WW) v = srcn[gy * WW + gx];
        }
        pre[i] = v;
      }
    }
    const float* wc = w_s + c * 144;
    const float* trow = tile[cur] + ty * 34 + tx;
#pragma unroll
    for (int kh = 0; kh < 3; kh++) {
#pragma unroll
      for (int kw = 0; kw < 3; kw++) {
        int t = kh * 3 + kw;
        const unsigned long long* wp2 = (const unsigned long long*)(wc + t * 16);
        unsigned long long wp[8];
#pragma unroll
        for (int o = 0; o < 8; o += 2) {
          ulonglong2 q = *(const ulonglong2*)(wp2 + o);
          wp[o] = q.x; wp[o + 1] = q.y;
        }
#pragma unroll
        for (int k = 0; k < 4; k++) {
          float v = trow[(8 * k + kh) * 34 + kw];
          unsigned long long vv;
          PACK_DUP(vv, v);
#pragma unroll
          for (int o = 0; o < 8; o++) FMA_F32X2(acc2[k][o], vv, wp[o]);
        }
      }
    }
    if (havePre) {
#pragma unroll
      for (int i = 0; i < 5; i++) {
        int idx = tid + 256 * i;
        if (idx < 34 * 34) tile[nxt][idx] = pre[i];
      }
    }
    __syncthreads();
  }

  const float* scp = g_scale + layer * CC + ocg * 16;
  const float* bip = g_bias + layer * CC + ocg * 16;
#pragma unroll
  for (int k = 0; k < 4; k++) {
    int y = y0 + ty + 8 * k;
    size_t pixb = ((size_t)b * HW + (size_t)y * WW + x0 + tx) * 64 + ocg * 16;
    float r[16];
#pragma unroll
    for (int o = 0; o < 8; o++) {
      unsigned lo, hi;
      UNPACK_2(lo, hi, acc2[k][o]);
      r[2 * o] = __uint_as_float(lo);
      r[2 * o + 1] = __uint_as_float(hi);
    }
    if (mode == 0) {
      __half hb[16], lb[16];
#pragma unroll
      for (int o = 0; o < 16; o++) {
        float v = r[o] * scp[o] + bip[o];
        v = v > 0.f ? v : 0.f;
        __half h = __float2half(v);
        hb[o] = h;
        lb[o] = __float2half(v - __half2float(h));
      }
      uint4* dh = (uint4*)(g_aH0 + pixb);
      uint4* dl = (uint4*)(g_aL0 + pixb);
      dh[0] = ((uint4*)hb)[0]; dh[1] = ((uint4*)hb)[1];
      dl[0] = ((uint4*)lb)[0]; dl[1] = ((uint4*)lb)[1];
    } else {
      uint4* df = (uint4*)(g_extra + pixb);
#pragma unroll
      for (int q = 0; q < 4; q++) df[q] = ((uint4*)r)[q];
    }
  }
}

// HMMA fp16 2-pass implicit-GEMM 3x3 conv, 64ic->64oc.
__launch_bounds__(256, 1)
__global__ void conv_mma_kernel(int srcSel, int wslot, int layer,
                                int use_extra, int do_proj,
                                const float* __restrict__ wf,
                                const float* __restrict__ bf,
                                float* __restrict__ out) {
  extern __shared__ __align__(16) char smem[];
  float* sc_s = (float*)(smem + 0);
  float* bi_s = (float*)(smem + 256);
  float* wf_s = (float*)(smem + 512);

  int tid = threadIdx.x, w = tid >> 5, lane = tid & 31;
  int tileX = blockIdx.x * 16, b = blockIdx.z;

  const __half* inH = srcSel ? g_aH1 : g_aH0;
  const __half* inL = srcSel ? g_aL1 : g_aL0;
  __half* outH = srcSel ? g_aH0 : g_aH1;
  __half* outL = srcSel ? g_aL0 : g_aL1;
  const __half* wHs = g_wH + wslot * 36864;

  // stage fp16 weights [tap][oc][ic], 144B-padded oc rows
  for (int i = tid; i < 4608; i += 256) {
    int t = i >> 9;
    int oc = (i >> 3) & 63;
    int ich = i & 7;
    uint4 v = *(const uint4*)(wHs + ((size_t)(t * 64 + oc) * 64 + ich * 8));
    *(uint4*)(smem + WGT_H + t * 9216 + oc * PST + ich * 16) = v;
  }
  if (tid < 64) { sc_s[tid] = g_scale[layer * CC + tid]; bi_s[tid] = g_bias[layer * CC + tid]; }
  if (do_proj && tid >= 64 && tid < 256) wf_s[tid - 64] = wf[tid - 64];

  uint32_t sb = smem_u32(smem);
  int mL = lane & 15;
  int rL = mL & 7, cL = w * 2 + (mL >> 3);
  uint32_t baseA = (uint32_t)((rL * 18 + cL) * PST + (lane >> 4) * 16);
  uint32_t baseB = (uint32_t)((lane & 7) * PST + ((lane >> 3) & 1) * 16 + (lane >> 4) * (8 * PST));
  int g = lane >> 2, t4 = lane & 3;

  for (int yt = 0; yt < 4; yt++) {
    int tileY = (blockIdx.y * 4 + yt) * 8;
    __syncthreads();

    for (int idx = tid; idx < 2880; idx += 256) {
      int half = idx >= 1440;
      int i = half ? idx - 1440 : idx;
      int r10 = i / 144;
      int rem = i - r10 * 144;
      int c18 = rem >> 3, och = rem & 7;
      int gy = tileY - 1 + r10, gx = tileX - 1 + c18;
      uint4 v = make_uint4(0, 0, 0, 0);
      if (gy >= 0 && gy < HH && gx >= 0 && gx < WW)
        v = *(const uint4*)((half ? inL : inH) + (((size_t)b * HW + (size_t)gy * WW + gx) * 64 + och * 8));
      *(uint4*)(smem + (half ? ACT_L : ACT_H) + (r10 * 18 + c18) * PST + och * 16) = v;
    }
    __syncthreads();

    float dacc[8][4];
#pragma unroll
    for (int nb = 0; nb < 8; nb++)
#pragma unroll
      for (int q = 0; q < 4; q++) dacc[nb][q] = 0.f;

    for (int t = 0; t < 9; t++) {
      int toff = ((t / 3) * 18 + (t % 3)) * PST;
      uint32_t aH_t = sb + ACT_H + baseA + toff;
      uint32_t aL_t = sb + ACT_L + baseA + toff;
      uint32_t wH_t = sb + WGT_H + t * 9216 + baseB;
#pragma unroll
      for (int kb = 0; kb < 4; kb++) {
        uint32_t ah[4], al[4], bh[4][4];
        LDM4(ah, aH_t + kb * 32);
        LDM4(al, aL_t + kb * 32);
#pragma unroll
        for (int j = 0; j < 4; j++) LDM4(bh[j], wH_t + j * 2304 + kb * 32);
        // pass 1: ah*wh
#pragma unroll
        for (int j = 0; j < 4; j++) {
          MMA16816(dacc[2 * j], ah, bh[j][0], bh[j][1]);
          MMA16816(dacc[2 * j + 1], ah, bh[j][2], bh[j][3]);
        }
        // pass 2: al*wh
#pragma unroll
        for (int j = 0; j < 4; j++) {
          MMA16816(dacc[2 * j], al, bh[j][0], bh[j][1]);
          MMA16816(dacc[2 * j + 1], al, bh[j][2], bh[j][3]);
        }
      }
    }

#pragma unroll
    for (int hrow = 0; hrow < 2; hrow++) {
      int mloc = w * 16 + g + hrow * 8;
      int r = mloc & 7, c = mloc >> 3;
      int py = tileY + r, px = tileX + c;
      size_t pix = (size_t)b * HW + (size_t)py * WW + px;
      float v[16];
#pragma unroll
      for (int nb = 0; nb < 8; nb++) {
        v[2 * nb] = dacc[nb][hrow * 2];
        v[2 * nb + 1] = dacc[nb][hrow * 2 + 1];
      }
      if (use_extra) {
#pragma unroll
        for (int nb = 0; nb < 8; nb++) {
          float2 e = *(const float2*)(g_extra + pix * 64 + nb * 8 + t4 * 2);
          v[2 * nb] += e.x; v[2 * nb + 1] += e.y;
        }
      }
#pragma unroll
      for (int i = 0; i < 16; i++) {
        int ch = (i >> 1) * 8 + t4 * 2 + (i & 1);
        float val = v[i] * sc_s[ch] + bi_s[ch];
        v[i] = val > 0.f ? val : 0.f;
      }
      if (do_proj) {
        float p0 = 0.f, p1 = 0.f, p2 = 0.f;
#pragma unroll
        for (int i = 0; i < 16; i++) {
          int ch = (i >> 1) * 8 + t4 * 2 + (i & 1);
          p0 += v[i] * wf_s[ch];
          p1 += v[i] * wf_s[64 + ch];
          p2 += v[i] * wf_s[128 + ch];
        }
#pragma unroll
        for (int m2 = 1; m2 <= 2; m2 <<= 1) {
          p0 += __shfl_xor_sync(0xffffffffu, p0, m2);
          p1 += __shfl_xor_sync(0xffffffffu, p1, m2);
          p2 += __shfl_xor_sync(0xffffffffu, p2, m2);
        }
        if (t4 == 0) {
          size_t ob = ((size_t)b * 3) * HW + (size_t)py * WW + px;
          out[ob] = p0 + bf[0];
          out[ob + HW] = p1 + bf[1];
          out[ob + 2 * HW] = p2 + bf[2];
        }
      } else {
#pragma unroll
        for (int nb = 0; nb < 8; nb++) {
          int ch = nb * 8 + t4 * 2;
          float v0 = v[2 * nb], v1 = v[2 * nb + 1];
          __half h0 = __float2half(v0), h1 = __float2half(v1);
          __half l0 = __float2half(v0 - __half2float(h0));
          __half l1 = __float2half(v1 - __half2float(h1));
          *(__half2*)(outH + pix * 64 + ch) = __halves2half2(h0, h1);
          *(__half2*)(outL + pix * 64 + ch) = __halves2half2(l0, l1);
        }
      }
    }
  }
}

__global__ void dft_rows_kernel() {
  int n = blockIdx.x, b = blockIdx.y;
  int m = threadIdx.x;
  __shared__ float row[256], twc[256], tws[256], red[16];
  float s, c;
  sincosf((float)m * (TWO_PI / 256.f), &s, &c);
  twc[m] = c; tws[m] = s;
  size_t off = ((size_t)b * HW + (size_t)n * WW + m) * 64;
  row[m] = __half2float(g_aH1[off]) + __half2float(g_aL1[off]);
  __syncthreads();
  float x = row[m];
  int lane = m & 31, wid = m >> 5;
  for (int f = 0; f < 21; f++) {
    int idx = ((118 + f) * m) & 255;
    float pr = x * twc[idx];
    float pi = -x * tws[idx];
#pragma unroll
    for (int o2 = 16; o2 > 0; o2 >>= 1) {
      pr += __shfl_down_sync(0xffffffffu, pr, o2);
      pi += __shfl_down_sync(0xffffffffu, pi, o2);
    }
    if (lane == 0) { red[wid] = pr; red[8 + wid] = pi; }
    __syncthreads();
    if (m == 0) {
      float sr = 0, si = 0;
      for (int w = 0; w < 8; w++) { sr += red[w]; si += red[8 + w]; }
      g_H[((size_t)(b * 21 + f) * 256 + n) * 2] = sr;
      g_H[((size_t)(b * 21 + f) * 256 + n) * 2 + 1] = si;
    }
    __syncthreads();
  }
}

__global__ void dft_points_kernel(const float* __restrict__ message) {
  int b = blockIdx.x;
  int p = threadIdx.x;
  __shared__ float twc[256], tws[256];
  float s, c;
  sincosf((float)p * (TWO_PI / 256.f), &s, &c);
  twc[p] = c; tws[p] = s;
  __syncthreads();
  int yp = g_wy[p], xp = g_wx[p];
  int f = xp - 118;
  const float* Hp = g_H + (size_t)(b * 21 + f) * 512;
  float Fr = 0, Fi = 0;
  for (int n = 0; n < 256; n++) {
    int idx = (yp * n) & 255;
    float cc = twc[idx], ss = tws[idx];
    float hr = Hp[n * 2], hi = Hp[n * 2 + 1];
    Fr += hr * cc + hi * ss;
    Fi += hi * cc - hr * ss;
  }
  float mv = message[b * LL + p];
  g_d[(b * NP + p) * 2] = mv - Fr;
  g_d[(b * NP + p) * 2 + 1] = mv - Fi;
}

__global__ void dft_R_kernel() {
  int yf = blockIdx.x, b = blockIdx.y;
  int m = threadIdx.x;
  __shared__ float twc[256], tws[256], dsr[256], dsi[256];
  float s, c;
  sincosf((float)m * (TWO_PI / 256.f), &s, &c);
  twc[m] = c; tws[m] = s;
  dsr[m] = g_d[(b * NP + m) * 2];
  dsi[m] = g_d[(b * NP + m) * 2 + 1];
  __syncthreads();
  int yv = 118 + yf;
  float ar = 0, ai = 0;
  for (int p = 0; p < NP; p++) {
    if (g_wy[p] == yv) {
      int idx = (g_wx[p] * m) & 255;
      float cc = twc[idx], ss = tws[idx];
      float dr = dsr[p], di = dsi[p];
      ar += dr * cc - di * ss;
      ai += dr * ss + di * cc;
    }
  }
  g_R[((size_t)(b * 16 + yf) * 256 + m) * 2] = ar;
  g_R[((size_t)(b * 16 + yf) * 256 + m) * 2 + 1] = ai;
}

__global__ void dft_corr_kernel() {
  int n = blockIdx.x, b = blockIdx.y;
  int m = threadIdx.x;
  __shared__ float twc[256], tws[256];
  float s, c;
  sincosf((float)m * (TWO_PI / 256.f), &s, &c);
  twc[m] = c; tws[m] = s;
  __syncthreads();
  float acc = 0.f;
#pragma unroll
  for (int yf = 0; yf < 16; yf++) {
    int idx = ((118 + yf) * n) & 255;
    float cc = twc[idx], ss = tws[idx];
    float Rr = g_R[((size_t)(b * 16 + yf) * 256 + m) * 2];
    float Ri = g_R[((size_t)(b * 16 + yf) * 256 + m) * 2 + 1];
    acc += cc * Rr - ss * Ri;
  }
  size_t off = ((size_t)b * HW + (size_t)n * WW + m) * 64;
  float v = __half2float(g_aH1[off]) + __half2float(g_aL1[off]) + acc * (1.0f / 65536.0f);
  __half h = __float2half(v);
  g_aH1[off] = h;
  g_aL1[off] = __float2half(v - __half2float(h));
}

extern "C" void kernel_launch(void* const* d_in, const int* in_sizes, int n_in,
                              void* d_out, int out_size) {
  const float* image   = (const float*)d_in[0];
  const float* message = (const float*)d_in[1];
  const float* w0  = (const float*)d_in[2];
  const float* b0  = (const float*)d_in[3];
  const float* g0  = (const float*)d_in[4];
  const float* be0 = (const float*)d_in[5];
  const float* m0  = (const float*)d_in[6];
  const float* v0  = (const float*)d_in[7];
  const float* wk  = (const float*)d_in[8];
  const float* bk  = (const float*)d_in[9];
  const float* gk  = (const float*)d_in[10];
  const float* bek = (const float*)d_in[11];
  const float* mk  = (const float*)d_in[12];
  const float* vk  = (const float*)d_in[13];
  const float* wa  = (const float*)d_in[14];
  const float* ba  = (const float*)d_in[15];
  const float* ga  = (const float*)d_in[16];
  const float* bea = (const float*)d_in[17];
  const float* ma  = (const float*)d_in[18];
  const float* va  = (const float*)d_in[19];
  const float* wf  = (const float*)d_in[20];
  const float* bf  = (const float*)d_in[21];
  float* out = (float*)d_out;

  cudaFuncSetAttribute(conv_mma_kernel, cudaFuncAttributeMaxDynamicSharedMemorySize, SMEM_MMA_TOTAL);

  prep_kernel<<<1, 256>>>(b0, g0, be0, m0, v0, bk, gk, bek, mk, vk, ba, ga, bea, ma, va);
  prep_w_kernel<<<576, 256>>>(wk, wa);
  msgT_kernel<<<dim3(64, NB), 256>>>(message, wa);

  conv3_scalar_kernel<<<dim3(4, 64, 2 * NB), 256>>>(image, w0, wa);

  dim3 mg(WW / 16, 8, NB);
  conv_mma_kernel<<<mg, 256, SMEM_MMA_TOTAL>>>(0, 0, 1, 0, 0, nullptr, nullptr, nullptr);
  conv_mma_kernel<<<mg, 256, SMEM_MMA_TOTAL>>>(1, 1, 2, 0, 0, nullptr, nullptr, nullptr);
  conv_mma_kernel<<<mg, 256, SMEM_MMA_TOTAL>>>(0, 2, 3, 0, 0, nullptr, nullptr, nullptr);

  dft_rows_kernel<<<dim3(256, NB), 256>>>();
  dft_points_kernel<<<NB, 256>>>(message);
  dft_R_kernel<<<dim3(16, NB), 256>>>();
  dft_corr_kernel<<<dim3(256, NB), 256>>>();

  conv_mma_kernel<<<mg, 256, SMEM_MMA_TOTAL>>>(1, 3, 4, 1, 1, wf, bf, out);
}

// round 9
// speedup vs baseline: 6.2338x; 1.5940x over previous
#include <cuda_runtime.h>
#include <cuda_fp16.h>
#include <math.h>
#include <stdint.h>

#define HH 256
#define WW 256
#define HW 65536
#define NB 16
#define CC 64
#define LL 256
#define NP 256

__device__ __half g_aH0[NB * HW * 64];
__device__ __half g_aH1[NB * HW * 64];
__device__ float g_extra[NB * HW * 64];
__device__ __half g_wH[4 * 9 * 64 * 64];   // [slot][tap][oc][ic] fp16
__device__ float g_H[NB * 21 * 256 * 2];
__device__ float g_d[NB * NP * 2];
__device__ float g_R[NB * 16 * 256 * 2];
__device__ float g_T[NB * CC * 9];
__device__ float g_scale[5 * CC];
__device__ float g_bias[5 * CC];
__device__ int   g_wy[NP];
__device__ int   g_wx[NP];

#define TWO_PI 6.283185307179586f

#define FMA_F32X2(d, a, b) \
  asm("fma.rn.f32x2 %0, %1, %2, %0;" : "+l"(d) : "l"(a), "l"(b))
#define ADD_F32X2_(d, a, b) \
  asm("add.rn.f32x2 %0, %1, %2;" : "=l"(d) : "l"(a), "l"(b))
#define PACK_DUP(out, v) \
  asm("mov.b64 %0, {%1, %1};" : "=l"(out) : "r"(__float_as_uint(v)))
#define UNPACK_2(lo, hi, in) \
  asm("mov.b64 {%0, %1}, %2;" : "=r"(lo), "=r"(hi) : "l"(in))

__device__ __forceinline__ uint32_t smem_u32(const void* p) {
  uint32_t a;
  asm("{ .reg .u64 t; cvta.to.shared.u64 t, %1; cvt.u32.u64 %0, t; }" : "=r"(a) : "l"(p));
  return a;
}
#define LDM4(r, addr) \
  asm volatile("ldmatrix.sync.aligned.m8n8.x4.shared.b16 {%0,%1,%2,%3}, [%4];" \
    : "=r"((r)[0]), "=r"((r)[1]), "=r"((r)[2]), "=r"((r)[3]) : "r"(addr))
#define MMA16816(d, a, b0, b1) \
  asm volatile("mma.sync.aligned.m16n8k16.row.col.f32.f16.f16.f32 " \
    "{%0,%1,%2,%3}, {%4,%5,%6,%7}, {%8,%9}, {%0,%1,%2,%3};" \
    : "+f"((d)[0]), "+f"((d)[1]), "+f"((d)[2]), "+f"((d)[3]) \
    : "r"((a)[0]), "r"((a)[1]), "r"((a)[2]), "r"((a)[3]), "r"(b0), "r"(b1))

#define ACT_H 1536
#define WGT_H 27456
#define SMEM_MMA_TOTAL 110400
#define PST 144

__global__ void prep_kernel(const float* b0, const float* g0, const float* be0,
                            const float* m0, const float* v0,
                            const float* bk, const float* gk, const float* bek,
                            const float* mk, const float* vk,
                            const float* ba, const float* ga, const float* bea,
                            const float* ma, const float* va) {
  int c = threadIdx.x;
  const float EPS = 1e-5f;
  if (c < CC) {
    float s = g0[c] * rsqrtf(v0[c] + EPS);
    g_scale[c] = s;
    g_bias[c] = be0[c] + (b0[c] - m0[c]) * s;
    for (int t = 0; t < 3; t++) {
      float st = gk[t * CC + c] * rsqrtf(vk[t * CC + c] + EPS);
      g_scale[(1 + t) * CC + c] = st;
      g_bias[(1 + t) * CC + c] = bek[t * CC + c] + (bk[t * CC + c] - mk[t * CC + c]) * st;
    }
    float sa = ga[c] * rsqrtf(va[c] + EPS);
    g_scale[4 * CC + c] = sa;
    g_bias[4 * CC + c] = bea[c] + (ba[c] - ma[c]) * sa;
  }
  if (c == 0) {
    int cnt = 0;
    for (int ch = 0; ch < CC && cnt < NP; ch++)
      for (int i = -10; i <= 10 && cnt < NP; i++)
        for (int j = -10; j <= 10; j++) {
          if (cnt >= NP) break;
          int y = 128 + i, x = 128 + j;
          if (y >= 0 && y < HH && x >= 0 && x < WW && (i * i + j * j <= 100)) {
            g_wy[cnt] = y; g_wx[cnt] = x; cnt++;
          }
        }
  }
}

__global__ void prep_w_kernel(const float* __restrict__ wk, const float* __restrict__ wa) {
  int i = blockIdx.x * 256 + threadIdx.x;
  int l = i / 36864;
  int rem = i - l * 36864;
  int t = rem / 4096;
  int r2 = rem & 4095;
  int oc = r2 >> 6, ic = r2 & 63;
  float w = (l < 3) ? wk[(((size_t)l * 64 + oc) * 64 + ic) * 9 + t]
                    : wa[((size_t)oc * 323 + 256 + ic) * 9 + t];
  g_wH[i] = __float2half(w);
}

__global__ void msgT_kernel(const float* __restrict__ message,
                            const float* __restrict__ wa) {
  int o = blockIdx.x, b = blockIdx.y;
  int c = threadIdx.x;
  __shared__ float red[8];
  float mv = message[b * LL + c];
  const float* wp = wa + ((size_t)o * 323 + c) * 9;
  for (int t = 0; t < 9; t++) {
    float v = mv * wp[t];
#pragma unroll
    for (int off = 16; off > 0; off >>= 1) v += __shfl_down_sync(0xffffffffu, v, off);
    if ((c & 31) == 0) red[c >> 5] = v;
    __syncthreads();
    if (c == 0) {
      float s = 0;
      for (int w2 = 0; w2 < 8; w2++) s += red[w2];
      g_T[(b * CC + o) * 9 + t] = s;
    }
    __syncthreads();
  }
}

// fused scalar FFMA2 conv: blockIdx.z in [0,32): b=z&15, mode=z>>4.
__launch_bounds__(256, 2)
__global__ void conv3_scalar_kernel(const float* __restrict__ ext_in,
                                    const float* __restrict__ w0,
                                    const float* __restrict__ wa) {
  __shared__ __align__(16) float w_s[3 * 144];
  __shared__ __align__(16) float tile[2][34 * 34 + 2];
  __shared__ __align__(16) float T_s[16 * 9];

  int tid = threadIdx.x;
  int ocg = blockIdx.x, tileId = blockIdx.y;
  int zz = blockIdx.z;
  int b = zz & 15, mode = zz >> 4;
  int y0 = (tileId >> 3) << 5, x0 = (tileId & 7) << 5;

  const float* Wt = mode ? wa : w0;
  int CW = mode ? 323 : 3;
  int ic0 = mode ? 320 : 0;
  int layer = mode ? 4 : 0;
  int use_msg = mode;

  int Wstride = CW * 9;
  for (int idx = tid; idx < 3 * 144; idx += 256) {
    int c = idx / 144;
    int rem = idx - c * 144;
    int t = rem >> 4;
    int oc = rem & 15;
    w_s[idx] = Wt[(size_t)(ocg * 16 + oc) * Wstride + (ic0 + c) * 9 + t];
  }
  if (use_msg && tid < 144)
    T_s[(tid % 9) * 16 + (tid / 9)] = g_T[(b * CC + ocg * 16 + (tid / 9)) * 9 + (tid % 9)];

  int tx = tid & 31, ty = tid >> 5;
  unsigned long long acc2[4][8];
#pragma unroll
  for (int k = 0; k < 4; k++)
#pragma unroll
    for (int o = 0; o < 8; o++) acc2[k][o] = 0ull;

  {
    const float* src0 = ext_in + ((size_t)(b * 3)) * HW;
    for (int idx = tid; idx < 34 * 34; idx += 256) {
      int r = idx / 34, cl = idx - r * 34;
      int gy = y0 + r - 1, gx = x0 + cl - 1;
      float v = 0.f;
      if (gy >= 0 && gy < HH && gx >= 0 && gx < WW) v = src0[gy * WW + gx];
      tile[0][idx] = v;
    }
  }
  __syncthreads();

  if (use_msg) {
#pragma unroll
    for (int kh = 0; kh < 3; kh++) {
#pragma unroll
      for (int kw = 0; kw < 3; kw++) {
        int t = kh * 3 + kw;
        const unsigned long long* tp = (const unsigned long long*)(T_s + t * 16);
        unsigned long long tpr[8];
#pragma unroll
        for (int o = 0; o < 8; o++) tpr[o] = tp[o];
#pragma unroll
        for (int k = 0; k < 4; k++) {
          int iy = y0 + ty + 8 * k + kh - 1;
          int ix = x0 + tx + kw - 1;
          if (iy >= 0 && iy < HH && ix >= 0 && ix < WW) {
#pragma unroll
            for (int o = 0; o < 8; o++) ADD_F32X2_(acc2[k][o], acc2[k][o], tpr[o]);
          }
        }
      }
    }
  }

  for (int c = 0; c < 3; c++) {
    int cur = c & 1, nxt = cur ^ 1;
    float pre[5];
    bool havePre = (c + 1 < 3);
    if (havePre) {
      const float* srcn = ext_in + ((size_t)(b * 3 + c + 1)) * HW;
#pragma unroll
      for (int i = 0; i < 5; i++) {
        int idx = tid + 256 * i;
        float v = 0.f;
        if (idx < 34 * 34) {
          int r = idx / 34, cl = idx - r * 34;
          int gy = y0 + r - 1, gx = x0 + cl - 1;
          if (gy >= 0 && gy < HH && gx >= 0 && gx < WW) v = srcn[gy * WW + gx];
        }
        pre[i] = v;
      }
    }
    const float* wc = w_s + c * 144;
    const float* trow = tile[cur] + ty * 34 + tx;
#pragma unroll
    for (int kh = 0; kh < 3; kh++) {
#pragma unroll
      for (int kw = 0; kw < 3; kw++) {
        int t = kh * 3 + kw;
        const unsigned long long* wp2 = (const unsigned long long*)(wc + t * 16);
        unsigned long long wp[8];
#pragma unroll
        for (int o = 0; o < 8; o += 2) {
          ulonglong2 q = *(const ulonglong2*)(wp2 + o);
          wp[o] = q.x; wp[o + 1] = q.y;
        }
#pragma unroll
        for (int k = 0; k < 4; k++) {
          float v = trow[(8 * k + kh) * 34 + kw];
          unsigned long long vv;
          PACK_DUP(vv, v);
#pragma unroll
          for (int o = 0; o < 8; o++) FMA_F32X2(acc2[k][o], vv, wp[o]);
        }
      }
    }
    if (havePre) {
#pragma unroll
      for (int i = 0; i < 5; i++) {
        int idx = tid + 256 * i;
        if (idx < 34 * 34) tile[nxt][idx] = pre[i];
      }
    }
    __syncthreads();
  }

  const float* scp = g_scale + layer * CC + ocg * 16;
  const float* bip = g_bias + layer * CC + ocg * 16;
#pragma unroll
  for (int k = 0; k < 4; k++) {
    int y = y0 + ty + 8 * k;
    size_t pixb = ((size_t)b * HW + (size_t)y * WW + x0 + tx) * 64 + ocg * 16;
    float r[16];
#pragma unroll
    for (int o = 0; o < 8; o++) {
      unsigned lo, hi;
      UNPACK_2(lo, hi, acc2[k][o]);
      r[2 * o] = __uint_as_float(lo);
      r[2 * o + 1] = __uint_as_float(hi);
    }
    if (mode == 0) {
      __half hb[16];
#pragma unroll
      for (int o = 0; o < 16; o++) {
        float v = r[o] * scp[o] + bip[o];
        v = v > 0.f ? v : 0.f;
        hb[o] = __float2half(v);
      }
      uint4* dh = (uint4*)(g_aH0 + pixb);
      dh[0] = ((uint4*)hb)[0]; dh[1] = ((uint4*)hb)[1];
    } else {
      uint4* df = (uint4*)(g_extra + pixb);
#pragma unroll
      for (int q = 0; q < 4; q++) df[q] = ((uint4*)r)[q];
    }
  }
}

// HMMA fp16 1-pass implicit-GEMM 3x3 conv, 64ic->64oc. 2 CTAs/SM.
__launch_bounds__(256, 2)
__global__ void conv_mma_kernel(int srcSel, int wslot, int layer,
                                int use_extra, int do_proj,
                                const float* __restrict__ wf,
                                const float* __restrict__ bf,
                                float* __restrict__ out) {
  extern __shared__ __align__(16) char smem[];
  float* sc_s = (float*)(smem + 0);
  float* bi_s = (float*)(smem + 256);
  float* wf_s = (float*)(smem + 512);

  int tid = threadIdx.x, w = tid >> 5, lane = tid & 31;
  int tileX = blockIdx.x * 16, b = blockIdx.z;

  const __half* inH = srcSel ? g_aH1 : g_aH0;
  __half* outH = srcSel ? g_aH0 : g_aH1;
  const __half* wHs = g_wH + wslot * 36864;

  // stage fp16 weights [tap][oc][ic], 144B-padded oc rows
  for (int i = tid; i < 4608; i += 256) {
    int t = i >> 9;
    int oc = (i >> 3) & 63;
    int ich = i & 7;
    uint4 v = *(const uint4*)(wHs + ((size_t)(t * 64 + oc) * 64 + ich * 8));
    *(uint4*)(smem + WGT_H + t * 9216 + oc * PST + ich * 16) = v;
  }
  if (tid < 64) { sc_s[tid] = g_scale[layer * CC + tid]; bi_s[tid] = g_bias[layer * CC + tid]; }
  if (do_proj && tid >= 64 && tid < 256) wf_s[tid - 64] = wf[tid - 64];

  uint32_t sb = smem_u32(smem);
  int mL = lane & 15;
  int rL = mL & 7, cL = w * 2 + (mL >> 3);
  uint32_t baseA = (uint32_t)((rL * 18 + cL) * PST + (lane >> 4) * 16);
  uint32_t baseB = (uint32_t)((lane & 7) * PST + ((lane >> 3) & 1) * 16 + (lane >> 4) * (8 * PST));
  int g = lane >> 2, t4 = lane & 3;

  for (int yt = 0; yt < 4; yt++) {
    int tileY = (blockIdx.y * 4 + yt) * 8;
    __syncthreads();

    // stage activation tile: 10 rows x 18 cols x 8 ch-chunks (fp16 hi only)
    for (int i = tid; i < 1440; i += 256) {
      int r10 = i / 144;
      int rem = i - r10 * 144;
      int c18 = rem >> 3, och = rem & 7;
      int gy = tileY - 1 + r10, gx = tileX - 1 + c18;
      uint4 v = make_uint4(0, 0, 0, 0);
      if (gy >= 0 && gy < HH && gx >= 0 && gx < WW)
        v = *(const uint4*)(inH + (((size_t)b * HW + (size_t)gy * WW + gx) * 64 + och * 8));
      *(uint4*)(smem + ACT_H + (r10 * 18 + c18) * PST + och * 16) = v;
    }
    __syncthreads();

    float dacc[8][4];
#pragma unroll
    for (int nb = 0; nb < 8; nb++)
#pragma unroll
      for (int q = 0; q < 4; q++) dacc[nb][q] = 0.f;

    for (int t = 0; t < 9; t++) {
      int toff = ((t / 3) * 18 + (t % 3)) * PST;
      uint32_t aH_t = sb + ACT_H + baseA + toff;
      uint32_t wH_t = sb + WGT_H + t * 9216 + baseB;
#pragma unroll
      for (int kb = 0; kb < 4; kb++) {
        uint32_t ah[4], bh[4][4];
        LDM4(ah, aH_t + kb * 32);
#pragma unroll
        for (int j = 0; j < 4; j++) LDM4(bh[j], wH_t + j * 2304 + kb * 32);
#pragma unroll
        for (int j = 0; j < 4; j++) {
          MMA16816(dacc[2 * j], ah, bh[j][0], bh[j][1]);
          MMA16816(dacc[2 * j + 1], ah, bh[j][2], bh[j][3]);
        }
      }
    }

#pragma unroll
    for (int hrow = 0; hrow < 2; hrow++) {
      int mloc = w * 16 + g + hrow * 8;
      int r = mloc & 7, c = mloc >> 3;
      int py = tileY + r, px = tileX + c;
      size_t pix = (size_t)b * HW + (size_t)py * WW + px;
      float v[16];
#pragma unroll
      for (int nb = 0; nb < 8; nb++) {
        v[2 * nb] = dacc[nb][hrow * 2];
        v[2 * nb + 1] = dacc[nb][hrow * 2 + 1];
      }
      if (use_extra) {
#pragma unroll
        for (int nb = 0; nb < 8; nb++) {
          float2 e = *(const float2*)(g_extra + pix * 64 + nb * 8 + t4 * 2);
          v[2 * nb] += e.x; v[2 * nb + 1] += e.y;
        }
      }
#pragma unroll
      for (int i = 0; i < 16; i++) {
        int ch = (i >> 1) * 8 + t4 * 2 + (i & 1);
        float val = v[i] * sc_s[ch] + bi_s[ch];
        v[i] = val > 0.f ? val : 0.f;
      }
      if (do_proj) {
        float p0 = 0.f, p1 = 0.f, p2 = 0.f;
#pragma unroll
        for (int i = 0; i < 16; i++) {
          int ch = (i >> 1) * 8 + t4 * 2 + (i & 1);
          p0 += v[i] * wf_s[ch];
          p1 += v[i] * wf_s[64 + ch];
          p2 += v[i] * wf_s[128 + ch];
        }
#pragma unroll
        for (int m2 = 1; m2 <= 2; m2 <<= 1) {
          p0 += __shfl_xor_sync(0xffffffffu, p0, m2);
          p1 += __shfl_xor_sync(0xffffffffu, p1, m2);
          p2 += __shfl_xor_sync(0xffffffffu, p2, m2);
        }
        if (t4 == 0) {
          size_t ob = ((size_t)b * 3) * HW + (size_t)py * WW + px;
          out[ob] = p0 + bf[0];
          out[ob + HW] = p1 + bf[1];
          out[ob + 2 * HW] = p2 + bf[2];
        }
      } else {
#pragma unroll
        for (int nb = 0; nb < 8; nb++) {
          int ch = nb * 8 + t4 * 2;
          *(__half2*)(outH + pix * 64 + ch) =
              __halves2half2(__float2half(v[2 * nb]), __float2half(v[2 * nb + 1]));
        }
      }
    }
  }
}

__global__ void dft_rows_kernel() {
  int n = blockIdx.x, b = blockIdx.y;
  int m = threadIdx.x;
  __shared__ float row[256], twc[256], tws[256], red[16];
  float s, c;
  sincosf((float)m * (TWO_PI / 256.f), &s, &c);
  twc[m] = c; tws[m] = s;
  size_t off = ((size_t)b * HW + (size_t)n * WW + m) * 64;
  row[m] = __half2float(g_aH1[off]);
  __syncthreads();
  float x = row[m];
  int lane = m & 31, wid = m >> 5;
  for (int f = 0; f < 21; f++) {
    int idx = ((118 + f) * m) & 255;
    float pr = x * twc[idx];
    float pi = -x * tws[idx];
#pragma unroll
    for (int o2 = 16; o2 > 0; o2 >>= 1) {
      pr += __shfl_down_sync(0xffffffffu, pr, o2);
      pi += __shfl_down_sync(0xffffffffu, pi, o2);
    }
    if (lane == 0) { red[wid] = pr; red[8 + wid] = pi; }
    __syncthreads();
    if (m == 0) {
      float sr = 0, si = 0;
      for (int w = 0; w < 8; w++) { sr += red[w]; si += red[8 + w]; }
      g_H[((size_t)(b * 21 + f) * 256 + n) * 2] = sr;
      g_H[((size_t)(b * 21 + f) * 256 + n) * 2 + 1] = si;
    }
    __syncthreads();
  }
}

__global__ void dft_points_kernel(const float* __restrict__ message) {
  int b = blockIdx.x;
  int p = threadIdx.x;
  __shared__ float twc[256], tws[256];
  float s, c;
  sincosf((float)p * (TWO_PI / 256.f), &s, &c);
  twc[p] = c; tws[p] = s;
  __syncthreads();
  int yp = g_wy[p], xp = g_wx[p];
  int f = xp - 118;
  const float* Hp = g_H + (size_t)(b * 21 + f) * 512;
  float Fr = 0, Fi = 0;
  for (int n = 0; n < 256; n++) {
    int idx = (yp * n) & 255;
    float cc = twc[idx], ss = tws[idx];
    float hr = Hp[n * 2], hi = Hp[n * 2 + 1];
    Fr += hr * cc + hi * ss;
    Fi += hi * cc - hr * ss;
  }
  float mv = message[b * LL + p];
  g_d[(b * NP + p) * 2] = mv - Fr;
  g_d[(b * NP + p) * 2 + 1] = mv - Fi;
}

__global__ void dft_R_kernel() {
  int yf = blockIdx.x, b = blockIdx.y;
  int m = threadIdx.x;
  __shared__ float twc[256], tws[256], dsr[256], dsi[256];
  float s, c;
  sincosf((float)m * (TWO_PI / 256.f), &s, &c);
  twc[m] = c; tws[m] = s;
  dsr[m] = g_d[(b * NP + m) * 2];
  dsi[m] = g_d[(b * NP + m) * 2 + 1];
  __syncthreads();
  int yv = 118 + yf;
  float ar = 0, ai = 0;
  for (int p = 0; p < NP; p++) {
    if (g_wy[p] == yv) {
      int idx = (g_wx[p] * m) & 255;
      float cc = twc[idx], ss = tws[idx];
      float dr = dsr[p], di = dsi[p];
      ar += dr * cc - di * ss;
      ai += dr * ss + di * cc;
    }
  }
  g_R[((size_t)(b * 16 + yf) * 256 + m) * 2] = ar;
  g_R[((size_t)(b * 16 + yf) * 256 + m) * 2 + 1] = ai;
}

__global__ void dft_corr_kernel() {
  int n = blockIdx.x, b = blockIdx.y;
  int m = threadIdx.x;
  __shared__ float twc[256], tws[256];
  float s, c;
  sincosf((float)m * (TWO_PI / 256.f), &s, &c);
  twc[m] = c; tws[m] = s;
  __syncthreads();
  float acc = 0.f;
#pragma unroll
  for (int yf = 0; yf < 16; yf++) {
    int idx = ((118 + yf) * n) & 255;
    float cc = twc[idx], ss = tws[idx];
    float Rr = g_R[((size_t)(b * 16 + yf) * 256 + m) * 2];
    float Ri = g_R[((size_t)(b * 16 + yf) * 256 + m) * 2 + 1];
    acc += cc * Rr - ss * Ri;
  }
  size_t off = ((size_t)b * HW + (size_t)n * WW + m) * 64;
  float v = __half2float(g_aH1[off]) + acc * (1.0f / 65536.0f);
  g_aH1[off] = __float2half(v);
}

extern "C" void kernel_launch(void* const* d_in, const int* in_sizes, int n_in,
                              void* d_out, int out_size) {
  const float* image   = (const float*)d_in[0];
  const float* message = (const float*)d_in[1];
  const float* w0  = (const float*)d_in[2];
  const float* b0  = (const float*)d_in[3];
  const float* g0  = (const float*)d_in[4];
  const float* be0 = (const float*)d_in[5];
  const float* m0  = (const float*)d_in[6];
  const float* v0  = (const float*)d_in[7];
  const float* wk  = (const float*)d_in[8];
  const float* bk  = (const float*)d_in[9];
  const float* gk  = (const float*)d_in[10];
  const float* bek = (const float*)d_in[11];
  const float* mk  = (const float*)d_in[12];
  const float* vk  = (const float*)d_in[13];
  const float* wa  = (const float*)d_in[14];
  const float* ba  = (const float*)d_in[15];
  const float* ga  = (const float*)d_in[16];
  const float* bea = (const float*)d_in[17];
  const float* ma  = (const float*)d_in[18];
  const float* va  = (const float*)d_in[19];
  const float* wf  = (const float*)d_in[20];
  const float* bf  = (const float*)d_in[21];
  float* out = (float*)d_out;

  cudaFuncSetAttribute(conv_mma_kernel, cudaFuncAttributeMaxDynamicSharedMemorySize, SMEM_MMA_TOTAL);

  prep_kernel<<<1, 256>>>(b0, g0, be0, m0, v0, bk, gk, bek, mk, vk, ba, ga, bea, ma, va);
  prep_w_kernel<<<576, 256>>>(wk, wa);
  msgT_kernel<<<dim3(64, NB), 256>>>(message, wa);

  conv3_scalar_kernel<<<dim3(4, 64, 2 * NB), 256>>>(image, w0, wa);

  dim3 mg(WW / 16, 8, NB);
  conv_mma_kernel<<<mg, 256, SMEM_MMA_TOTAL>>>(0, 0, 1, 0, 0, nullptr, nullptr, nullptr);
  conv_mma_kernel<<<mg, 256, SMEM_MMA_TOTAL>>>(1, 1, 2, 0, 0, nullptr, nullptr, nullptr);
  conv_mma_kernel<<<mg, 256, SMEM_MMA_TOTAL>>>(0, 2, 3, 0, 0, nullptr, nullptr, nullptr);

  dft_rows_kernel<<<dim3(256, NB), 256>>>();
  dft_points_kernel<<<NB, 256>>>(message);
  dft_R_kernel<<<dim3(16, NB), 256>>>();
  dft_corr_kernel<<<dim3(256, NB), 256>>>();

  conv_mma_kernel<<<mg, 256, SMEM_MMA_TOTAL>>>(1, 3, 4, 1, 1, wf, bf, out);
}

// round 10
// speedup vs baseline: 7.3062x; 1.1720x over previous
#include <cuda_runtime.h>
#include <cuda_fp16.h>
#include <math.h>
#include <stdint.h>

#define HH 256
#define WW 256
#define HW 65536
#define NB 16
#define CC 64
#define LL 256
#define NP 256

__device__ __half g_aH0[NB * HW * 64];
__device__ __half g_aH1[NB * HW * 64];
__device__ float g_extra[NB * HW * 64];     // layer-4 image side field (conv only, no msg)
__device__ __half g_wH[4 * 9 * 64 * 64];    // [slot][tap][oc][ic] fp16
__device__ __half g_w3[128 * 32];           // conv0+side fused B: [n][k], k=ch*9+tap
__device__ float g_H[NB * 21 * 256 * 2];
__device__ float g_d[NB * NP * 2];
__device__ float g_R[NB * 16 * 256 * 2];
__device__ float g_T[NB * CC * 9];
__device__ float g_Tsum[NB * CC];
__device__ float g_scale[5 * CC];
__device__ float g_bias[5 * CC];
__device__ int   g_wy[NP];
__device__ int   g_wx[NP];

#define TWO_PI 6.283185307179586f

__device__ __forceinline__ uint32_t smem_u32(const void* p) {
  uint32_t a;
  asm("{ .reg .u64 t; cvta.to.shared.u64 t, %1; cvt.u32.u64 %0, t; }" : "=r"(a) : "l"(p));
  return a;
}
#define LDM4(r, addr) \
  asm volatile("ldmatrix.sync.aligned.m8n8.x4.shared.b16 {%0,%1,%2,%3}, [%4];" \
    : "=r"((r)[0]), "=r"((r)[1]), "=r"((r)[2]), "=r"((r)[3]) : "r"(addr))
#define MMA16816(d, a, b0, b1) \
  asm volatile("mma.sync.aligned.m16n8k16.row.col.f32.f16.f16.f32 " \
    "{%0,%1,%2,%3}, {%4,%5,%6,%7}, {%8,%9}, {%0,%1,%2,%3};" \
    : "+f"((d)[0]), "+f"((d)[1]), "+f"((d)[2]), "+f"((d)[3]) \
    : "r"((a)[0]), "r"((a)[1]), "r"((a)[2]), "r"((a)[3]), "r"(b0), "r"(b1))

// conv_mma smem layout
#define SC_OFF 0
#define BI_OFF 256
#define WF_OFF 512
#define T_OFF  1280
#define TS_OFF 3584
#define ACT_H  4096
#define WGT_H  30016
#define SMEM_MMA_TOTAL 112960
#define PST 144

__global__ void prep_kernel(const float* b0, const float* g0, const float* be0,
                            const float* m0, const float* v0,
                            const float* bk, const float* gk, const float* bek,
                            const float* mk, const float* vk,
                            const float* ba, const float* ga, const float* bea,
                            const float* ma, const float* va) {
  int c = threadIdx.x;
  const float EPS = 1e-5f;
  if (c < CC) {
    float s = g0[c] * rsqrtf(v0[c] + EPS);
    g_scale[c] = s;
    g_bias[c] = be0[c] + (b0[c] - m0[c]) * s;
    for (int t = 0; t < 3; t++) {
      float st = gk[t * CC + c] * rsqrtf(vk[t * CC + c] + EPS);
      g_scale[(1 + t) * CC + c] = st;
      g_bias[(1 + t) * CC + c] = bek[t * CC + c] + (bk[t * CC + c] - mk[t * CC + c]) * st;
    }
    float sa = ga[c] * rsqrtf(va[c] + EPS);
    g_scale[4 * CC + c] = sa;
    g_bias[4 * CC + c] = bea[c] + (ba[c] - ma[c]) * sa;
  }
  if (c == 0) {
    int cnt = 0;
    for (int ch = 0; ch < CC && cnt < NP; ch++)
      for (int i = -10; i <= 10 && cnt < NP; i++)
        for (int j = -10; j <= 10; j++) {
          if (cnt >= NP) break;
          int y = 128 + i, x = 128 + j;
          if (y >= 0 && y < HH && x >= 0 && x < WW && (i * i + j * j <= 100)) {
            g_wy[cnt] = y; g_wx[cnt] = x; cnt++;
          }
        }
  }
}

__global__ void prep_w_kernel(const float* __restrict__ wk, const float* __restrict__ wa) {
  int i = blockIdx.x * 256 + threadIdx.x;
  int l = i / 36864;
  int rem = i - l * 36864;
  int t = rem / 4096;
  int r2 = rem & 4095;
  int oc = r2 >> 6, ic = r2 & 63;
  float w = (l < 3) ? wk[(((size_t)l * 64 + oc) * 64 + ic) * 9 + t]
                    : wa[((size_t)oc * 323 + 256 + ic) * 9 + t];
  g_wH[i] = __float2half(w);
}

// fused conv0+side weights: B[n][k], k = ch*9 + kh*3 + kw, padded to 32
__global__ void prep_w3_kernel(const float* __restrict__ w0, const float* __restrict__ wa) {
  int i = blockIdx.x * 256 + threadIdx.x;
  if (i >= 128 * 32) return;
  int n = i >> 5, k = i & 31;
  float v = 0.f;
  if (k < 27) {
    int c = k / 9, t = k % 9, kh = t / 3, kw = t % 3;
    v = (n < 64) ? w0[((n * 3 + c) * 3 + kh) * 3 + kw]
                 : wa[(((size_t)(n - 64) * 323 + 320 + c) * 3 + kh) * 3 + kw];
  }
  g_w3[i] = __float2half(v);
}

__global__ void msgT_kernel(const float* __restrict__ message,
                            const float* __restrict__ wa) {
  int o = blockIdx.x, b = blockIdx.y;
  int c = threadIdx.x;
  __shared__ float red[8];
  float mv = message[b * LL + c];
  const float* wp = wa + ((size_t)o * 323 + c) * 9;
  float tsum = 0.f;
  for (int t = 0; t < 9; t++) {
    float v = mv * wp[t];
#pragma unroll
    for (int off = 16; off > 0; off >>= 1) v += __shfl_down_sync(0xffffffffu, v, off);
    if ((c & 31) == 0) red[c >> 5] = v;
    __syncthreads();
    if (c == 0) {
      float s = 0;
      for (int w2 = 0; w2 < 8; w2++) s += red[w2];
      g_T[(b * CC + o) * 9 + t] = s;
      tsum += s;
    }
    __syncthreads();
  }
  if (c == 0) g_Tsum[b * CC + o] = tsum;
}

// fused conv0 + layer-4 image side-field via HMMA implicit GEMM.
// A: [128 px][K=32] im2col (3ch x 9taps), B: [32][128] (64 conv0 oc | 64 side oc).
#define C3_A 2160
#define C3_B 12400
#define C3_SC 22640
__launch_bounds__(256, 2)
__global__ void conv3_mma_kernel(const float* __restrict__ image) {
  __shared__ __align__(16) char s3[23152];
  float* tile = (float*)s3;                 // [3][10][18] fp32
  float* sc3 = (float*)(s3 + C3_SC);
  float* bi3 = (float*)(s3 + C3_SC + 256);

  int tid = threadIdx.x, w = tid >> 5, lane = tid & 31;
  int tileX = blockIdx.x * 16, tileY = blockIdx.y * 8, b = blockIdx.z;

  for (int idx = tid; idx < 540; idx += 256) {
    int ch = idx / 180, rem = idx % 180;
    int r10 = rem / 18, c18 = rem % 18;
    int gy = tileY - 1 + r10, gx = tileX - 1 + c18;
    float v = 0.f;
    if (gy >= 0 && gy < HH && gx >= 0 && gx < WW)
      v = image[((size_t)(b * 3 + ch)) * HW + (size_t)gy * WW + gx];
    tile[idx] = v;
  }
  for (int idx = tid; idx < 2048; idx += 256) {  // B: 128 rows x 16 half2
    int n = idx >> 4, kp = idx & 15;
    *(uint32_t*)(s3 + C3_B + n * 80 + kp * 4) = *(const uint32_t*)(g_w3 + n * 32 + kp * 2);
  }
  if (tid < 64) { sc3[tid] = g_scale[tid]; bi3[tid] = g_bias[tid]; }
  __syncthreads();

  if (tid < 128) {  // build A rows (im2col, fp16)
    int m = tid, r = m & 7, c = m >> 3;
    __half arow[32];
#pragma unroll
    for (int ch = 0; ch < 3; ch++)
#pragma unroll
      for (int t = 0; t < 9; t++)
        arow[ch * 9 + t] = __float2half(tile[ch * 180 + (r + t / 3) * 18 + (c + t % 3)]);
#pragma unroll
    for (int k = 27; k < 32; k++) arow[k] = __float2half(0.f);
    uint4* dst = (uint4*)(s3 + C3_A + m * 80);
    dst[0] = ((uint4*)arow)[0]; dst[1] = ((uint4*)arow)[1];
    dst[2] = ((uint4*)arow)[2]; dst[3] = ((uint4*)arow)[3];
  }
  __syncthreads();

  uint32_t sb = smem_u32(s3);
  uint32_t baseA = sb + C3_A + (w * 16 + (lane & 15)) * 80 + (lane >> 4) * 16;
  uint32_t baseB = sb + C3_B + (lane & 7) * 80 + ((lane >> 3) & 1) * 16 + (lane >> 4) * 640;

  float dacc[16][4];
#pragma unroll
  for (int nb = 0; nb < 16; nb++)
#pragma unroll
    for (int q = 0; q < 4; q++) dacc[nb][q] = 0.f;

#pragma unroll
  for (int kb = 0; kb < 2; kb++) {
    uint32_t a[4];
    LDM4(a, baseA + kb * 32);
#pragma unroll
    for (int j = 0; j < 8; j++) {
      uint32_t bb[4];
      LDM4(bb, baseB + j * 1280 + kb * 32);
      MMA16816(dacc[2 * j], a, bb[0], bb[1]);
      MMA16816(dacc[2 * j + 1], a, bb[2], bb[3]);
    }
  }

  int g = lane >> 2, t4 = lane & 3;
#pragma unroll
  for (int hrow = 0; hrow < 2; hrow++) {
    int m = w * 16 + g + hrow * 8;
    int r = m & 7, c = m >> 3;
    int py = tileY + r, px = tileX + c;
    size_t pix = (size_t)b * HW + (size_t)py * WW + px;
#pragma unroll
    for (int nb = 0; nb < 8; nb++) {  // conv0: BN+ReLU -> fp16
      int ch = nb * 8 + t4 * 2;
      float v0 = dacc[nb][hrow * 2] * sc3[ch] + bi3[ch];
      float v1 = dacc[nb][hrow * 2 + 1] * sc3[ch + 1] + bi3[ch + 1];
      v0 = v0 > 0.f ? v0 : 0.f;
      v1 = v1 > 0.f ? v1 : 0.f;
      *(__half2*)(g_aH0 + pix * 64 + ch) = __halves2half2(__float2half(v0), __float2half(v1));
    }
#pragma unroll
    for (int nb = 8; nb < 16; nb++) {  // side field raw fp32
      int oce = (nb - 8) * 8 + t4 * 2;
      *(float2*)(g_extra + pix * 64 + oce) = make_float2(dacc[nb][hrow * 2], dacc[nb][hrow * 2 + 1]);
    }
  }
}

// HMMA fp16 1-pass implicit-GEMM 3x3 conv, 64ic->64oc. 2 CTAs/SM, double-buffered staging.
__launch_bounds__(256, 2)
__global__ void conv_mma_kernel(int srcSel, int wslot, int layer,
                                int use_extra, int do_proj,
                                const float* __restrict__ wf,
                                const float* __restrict__ bf,
                                float* __restrict__ out) {
  extern __shared__ __align__(16) char smem[];
  float* sc_s = (float*)(smem + SC_OFF);
  float* bi_s = (float*)(smem + BI_OFF);
  float* wf_s = (float*)(smem + WF_OFF);
  float* T_s = (float*)(smem + T_OFF);
  float* Ts_s = (float*)(smem + TS_OFF);

  int tid = threadIdx.x, w = tid >> 5, lane = tid & 31;
  int tileX = blockIdx.x * 16, b = blockIdx.z;

  const __half* inH = srcSel ? g_aH1 : g_aH0;
  __half* outH = srcSel ? g_aH0 : g_aH1;
  const __half* wHs = g_wH + wslot * 36864;

  for (int i = tid; i < 4608; i += 256) {
    int t = i >> 9;
    int oc = (i >> 3) & 63;
    int ich = i & 7;
    uint4 v = *(const uint4*)(wHs + ((size_t)(t * 64 + oc) * 64 + ich * 8));
    *(uint4*)(smem + WGT_H + t * 9216 + oc * PST + ich * 16) = v;
  }
  if (tid < 64) { sc_s[tid] = g_scale[layer * CC + tid]; bi_s[tid] = g_bias[layer * CC + tid]; }
  if (do_proj && tid >= 64 && tid < 256) wf_s[tid - 64] = wf[tid - 64];
  if (use_extra) {
    for (int i = tid; i < 576; i += 256) T_s[i] = g_T[b * 576 + i];
    if (tid < 64) Ts_s[tid] = g_Tsum[b * CC + tid];
  }

  uint32_t sb = smem_u32(smem);
  int mL = lane & 15;
  int rL = mL & 7, cL = w * 2 + (mL >> 3);
  uint32_t baseA = (uint32_t)((rL * 18 + cL) * PST + (lane >> 4) * 16);
  uint32_t baseB = (uint32_t)((lane & 7) * PST + ((lane >> 3) & 1) * 16 + (lane >> 4) * (8 * PST));
  int g = lane >> 2, t4 = lane & 3;

  // stage first y-tile
  {
    int tileY0 = (blockIdx.y * 4) * 8;
    for (int i = tid; i < 1440; i += 256) {
      int r10 = i / 144;
      int rem = i - r10 * 144;
      int c18 = rem >> 3, och = rem & 7;
      int gy = tileY0 - 1 + r10, gx = tileX - 1 + c18;
      uint4 v = make_uint4(0, 0, 0, 0);
      if (gy >= 0 && gy < HH && gx >= 0 && gx < WW)
        v = *(const uint4*)(inH + (((size_t)b * HW + (size_t)gy * WW + gx) * 64 + och * 8));
      *(uint4*)(smem + ACT_H + (r10 * 18 + c18) * PST + och * 16) = v;
    }
  }
  __syncthreads();

  for (int yt = 0; yt < 4; yt++) {
    int tileY = (blockIdx.y * 4 + yt) * 8;

    // prefetch next y-tile into registers
    uint4 pre[6];
    if (yt < 3) {
      int tileYn = tileY + 8;
#pragma unroll
      for (int i2 = 0; i2 < 6; i2++) {
        int idx = tid + 256 * i2;
        uint4 v = make_uint4(0, 0, 0, 0);
        if (idx < 1440) {
          int r10 = idx / 144;
          int rem = idx - r10 * 144;
          int c18 = rem >> 3, och = rem & 7;
          int gy = tileYn - 1 + r10, gx = tileX - 1 + c18;
          if (gy >= 0 && gy < HH && gx >= 0 && gx < WW)
            v = *(const uint4*)(inH + (((size_t)b * HW + (size_t)gy * WW + gx) * 64 + och * 8));
        }
        pre[i2] = v;
      }
    }

    float dacc[8][4];
#pragma unroll
    for (int nb = 0; nb < 8; nb++)
#pragma unroll
      for (int q = 0; q < 4; q++) dacc[nb][q] = 0.f;

    for (int t = 0; t < 9; t++) {
      int toff = ((t / 3) * 18 + (t % 3)) * PST;
      uint32_t aH_t = sb + ACT_H + baseA + toff;
      uint32_t wH_t = sb + WGT_H + t * 9216 + baseB;
#pragma unroll
      for (int kb = 0; kb < 4; kb++) {
        uint32_t ah[4], bh[4][4];
        LDM4(ah, aH_t + kb * 32);
#pragma unroll
        for (int j = 0; j < 4; j++) LDM4(bh[j], wH_t + j * 2304 + kb * 32);
#pragma unroll
        for (int j = 0; j < 4; j++) {
          MMA16816(dacc[2 * j], ah, bh[j][0], bh[j][1]);
          MMA16816(dacc[2 * j + 1], ah, bh[j][2], bh[j][3]);
        }
      }
    }

    __syncthreads();
    if (yt < 3) {
#pragma unroll
      for (int i2 = 0; i2 < 6; i2++) {
        int idx = tid + 256 * i2;
        if (idx < 1440) {
          int r10 = idx / 144;
          int rem = idx - r10 * 144;
          int c18 = rem >> 3, och = rem & 7;
          *(uint4*)(smem + ACT_H + (r10 * 18 + c18) * PST + och * 16) = pre[i2];
        }
      }
      __syncthreads();
    }

#pragma unroll
    for (int hrow = 0; hrow < 2; hrow++) {
      int mloc = w * 16 + g + hrow * 8;
      int r = mloc & 7, c = mloc >> 3;
      int py = tileY + r, px = tileX + c;
      size_t pix = (size_t)b * HW + (size_t)py * WW + px;
      float v[16];
#pragma unroll
      for (int nb = 0; nb < 8; nb++) {
        v[2 * nb] = dacc[nb][hrow * 2];
        v[2 * nb + 1] = dacc[nb][hrow * 2 + 1];
      }
      if (use_extra) {
#pragma unroll
        for (int nb = 0; nb < 8; nb++) {
          float2 e = *(const float2*)(g_extra + pix * 64 + nb * 8 + t4 * 2);
          v[2 * nb] += e.x; v[2 * nb + 1] += e.y;
        }
        bool interior = (py >= 1 && py <= 254 && px >= 1 && px <= 254);
        if (interior) {
#pragma unroll
          for (int i = 0; i < 16; i++) {
            int ch = (i >> 1) * 8 + t4 * 2 + (i & 1);
            v[i] += Ts_s[ch];
          }
        } else {
          bool vy[3] = {py >= 1, true, py <= 254};
          bool vx[3] = {px >= 1, true, px <= 254};
#pragma unroll
          for (int i = 0; i < 16; i++) {
            int ch = (i >> 1) * 8 + t4 * 2 + (i & 1);
            float s = 0.f;
#pragma unroll
            for (int t = 0; t < 9; t++)
              if (vy[t / 3] && vx[t % 3]) s += T_s[ch * 9 + t];
            v[i] += s;
          }
        }
      }
#pragma unroll
      for (int i = 0; i < 16; i++) {
        int ch = (i >> 1) * 8 + t4 * 2 + (i & 1);
        float val = v[i] * sc_s[ch] + bi_s[ch];
        v[i] = val > 0.f ? val : 0.f;
      }
      if (do_proj) {
        float p0 = 0.f, p1 = 0.f, p2 = 0.f;
#pragma unroll
        for (int i = 0; i < 16; i++) {
          int ch = (i >> 1) * 8 + t4 * 2 + (i & 1);
          p0 += v[i] * wf_s[ch];
          p1 += v[i] * wf_s[64 + ch];
          p2 += v[i] * wf_s[128 + ch];
        }
#pragma unroll
        for (int m2 = 1; m2 <= 2; m2 <<= 1) {
          p0 += __shfl_xor_sync(0xffffffffu, p0, m2);
          p1 += __shfl_xor_sync(0xffffffffu, p1, m2);
          p2 += __shfl_xor_sync(0xffffffffu, p2, m2);
        }
        if (t4 == 0) {
          size_t ob = ((size_t)b * 3) * HW + (size_t)py * WW + px;
          out[ob] = p0 + bf[0];
          out[ob + HW] = p1 + bf[1];
          out[ob + 2 * HW] = p2 + bf[2];
        }
      } else {
#pragma unroll
        for (int nb = 0; nb < 8; nb++) {
          int ch = nb * 8 + t4 * 2;
          *(__half2*)(outH + pix * 64 + ch) =
              __halves2half2(__float2half(v[2 * nb]), __float2half(v[2 * nb + 1]));
        }
      }
    }
  }
}

__global__ void dft_rows_kernel() {
  int n = blockIdx.x, b = blockIdx.y;
  int m = threadIdx.x;
  __shared__ float row[256], twc[256], tws[256], red[16];
  float s, c;
  sincosf((float)m * (TWO_PI / 256.f), &s, &c);
  twc[m] = c; tws[m] = s;
  size_t off = ((size_t)b * HW + (size_t)n * WW + m) * 64;
  row[m] = __half2float(g_aH1[off]);
  __syncthreads();
  float x = row[m];
  int lane = m & 31, wid = m >> 5;
  for (int f = 0; f < 21; f++) {
    int idx = ((118 + f) * m) & 255;
    float pr = x * twc[idx];
    float pi = -x * tws[idx];
#pragma unroll
    for (int o2 = 16; o2 > 0; o2 >>= 1) {
      pr += __shfl_down_sync(0xffffffffu, pr, o2);
      pi += __shfl_down_sync(0xffffffffu, pi, o2);
    }
    if (lane == 0) { red[wid] = pr; red[8 + wid] = pi; }
    __syncthreads();
    if (m == 0) {
      float sr = 0, si = 0;
      for (int w = 0; w < 8; w++) { sr += red[w]; si += red[8 + w]; }
      g_H[((size_t)(b * 21 + f) * 256 + n) * 2] = sr;
      g_H[((size_t)(b * 21 + f) * 256 + n) * 2 + 1] = si;
    }
    __syncthreads();
  }
}

__global__ void dft_points_kernel(const float* __restrict__ message) {
  int b = blockIdx.x;
  int p = threadIdx.x;
  __shared__ float twc[256], tws[256];
  float s, c;
  sincosf((float)p * (TWO_PI / 256.f), &s, &c);
  twc[p] = c; tws[p] = s;
  __syncthreads();
  int yp = g_wy[p], xp = g_wx[p];
  int f = xp - 118;
  const float* Hp = g_H + (size_t)(b * 21 + f) * 512;
  float Fr = 0, Fi = 0;
  for (int n = 0; n < 256; n++) {
    int idx = (yp * n) & 255;
    float cc = twc[idx], ss = tws[idx];
    float hr = Hp[n * 2], hi = Hp[n * 2 + 1];
    Fr += hr * cc + hi * ss;
    Fi += hi * cc - hr * ss;
  }
  float mv = message[b * LL + p];
  g_d[(b * NP + p) * 2] = mv - Fr;
  g_d[(b * NP + p) * 2 + 1] = mv - Fi;
}

__global__ void dft_R_kernel() {
  int yf = blockIdx.x, b = blockIdx.y;
  int m = threadIdx.x;
  __shared__ float twc[256], tws[256], dsr[256], dsi[256];
  float s, c;
  sincosf((float)m * (TWO_PI / 256.f), &s, &c);
  twc[m] = c; tws[m] = s;
  dsr[m] = g_d[(b * NP + m) * 2];
  dsi[m] = g_d[(b * NP + m) * 2 + 1];
  __syncthreads();
  int yv = 118 + yf;
  float ar = 0, ai = 0;
  for (int p = 0; p < NP; p++) {
    if (g_wy[p] == yv) {
      int idx = (g_wx[p] * m) & 255;
      float cc = twc[idx], ss = tws[idx];
      float dr = dsr[p], di = dsi[p];
      ar += dr * cc - di * ss;
      ai += dr * ss + di * cc;
    }
  }
  g_R[((size_t)(b * 16 + yf) * 256 + m) * 2] = ar;
  g_R[((size_t)(b * 16 + yf) * 256 + m) * 2 + 1] = ai;
}

__global__ void dft_corr_kernel() {
  int n = blockIdx.x, b = blockIdx.y;
  int m = threadIdx.x;
  __shared__ float twc[256], tws[256];
  float s, c;
  sincosf((float)m * (TWO_PI / 256.f), &s, &c);
  twc[m] = c; tws[m] = s;
  __syncthreads();
  float acc = 0.f;
#pragma unroll
  for (int yf = 0; yf < 16; yf++) {
    int idx = ((118 + yf) * n) & 255;
    float cc = twc[idx], ss = tws[idx];
    float Rr = g_R[((size_t)(b * 16 + yf) * 256 + m) * 2];
    float Ri = g_R[((size_t)(b * 16 + yf) * 256 + m) * 2 + 1];
    acc += cc * Rr - ss * Ri;
  }
  size_t off = ((size_t)b * HW + (size_t)n * WW + m) * 64;
  float v = __half2float(g_aH1[off]) + acc * (1.0f / 65536.0f);
  g_aH1[off] = __float2half(v);
}

extern "C" void kernel_launch(void* const* d_in, const int* in_sizes, int n_in,
                              void* d_out, int out_size) {
  const float* image   = (const float*)d_in[0];
  const float* message = (const float*)d_in[1];
  const float* w0  = (const float*)d_in[2];
  const float* b0  = (const float*)d_in[3];
  const float* g0  = (const float*)d_in[4];
  const float* be0 = (const float*)d_in[5];
  const float* m0  = (const float*)d_in[6];
  const float* v0  = (const float*)d_in[7];
  const float* wk  = (const float*)d_in[8];
  const float* bk  = (const float*)d_in[9];
  const float* gk  = (const float*)d_in[10];
  const float* bek = (const float*)d_in[11];
  const float* mk  = (const float*)d_in[12];
  const float* vk  = (const float*)d_in[13];
  const float* wa  = (const float*)d_in[14];
  const float* ba  = (const float*)d_in[15];
  const float* ga  = (const float*)d_in[16];
  const float* bea = (const float*)d_in[17];
  const float* ma  = (const float*)d_in[18];
  const float* va  = (const float*)d_in[19];
  const float* wf  = (const float*)d_in[20];
  const float* bf  = (const float*)d_in[21];
  float* out = (float*)d_out;

  cudaFuncSetAttribute(conv_mma_kernel, cudaFuncAttributeMaxDynamicSharedMemorySize, SMEM_MMA_TOTAL);

  prep_kernel<<<1, 256>>>(b0, g0, be0, m0, v0, bk, gk, bek, mk, vk, ba, ga, bea, ma, va);
  prep_w_kernel<<<576, 256>>>(wk, wa);
  prep_w3_kernel<<<16, 256>>>(w0, wa);
  msgT_kernel<<<dim3(64, NB), 256>>>(message, wa);

  // fused conv0 + layer-4 image side field (HMMA, K=32)
  conv3_mma_kernel<<<dim3(16, 32, NB), 256>>>(image);

  dim3 mg(WW / 16, 8, NB);
  conv_mma_kernel<<<mg, 256, SMEM_MMA_TOTAL>>>(0, 0, 1, 0, 0, nullptr, nullptr, nullptr);
  conv_mma_kernel<<<mg, 256, SMEM_MMA_TOTAL>>>(1, 1, 2, 0, 0, nullptr, nullptr, nullptr);
  conv_mma_kernel<<<mg, 256, SMEM_MMA_TOTAL>>>(0, 2, 3, 0, 0, nullptr, nullptr, nullptr);

  dft_rows_kernel<<<dim3(256, NB), 256>>>();
  dft_points_kernel<<<NB, 256>>>(message);
  dft_R_kernel<<<dim3(16, NB), 256>>>();
  dft_corr_kernel<<<dim3(256, NB), 256>>>();

  conv_mma_kernel<<<mg, 256, SMEM_MMA_TOTAL>>>(1, 3, 4, 1, 1, wf, bf, out);
}